// round 8
// baseline (speedup 1.0000x reference)
#include <cuda_runtime.h>
#include <cuda_fp16.h>
#include <cstdint>
#include <cstddef>

// ---------------------------------------------------------------------------
// Problem constants
// ---------------------------------------------------------------------------
#define BSZ 2
#define NP  128
#define DIM 1024
#define GEO 64
#define TOPK 18
#define MBIG (BSZ * NP * NP)     // 32768 pairwise rows
#define MSMALL (BSZ * NP)        // 256 proposal rows

// ---------------------------------------------------------------------------
// Scratch (static device globals)
// ---------------------------------------------------------------------------
__device__ float g_FA[MSMALL * DIM];
__device__ float g_FB[MSMALL * DIM];
__device__ float g_T[MSMALL * DIM];
__device__ float g_CAT[MSMALL * 2 * DIM];
__device__ float g_SA[MSMALL * DIM];
__device__ float g_SB[MSMALL * DIM];
__device__ float g_P[32 * MSMALL * DIM];         // split-K partials (32 MB)
__device__ unsigned short g_G3[MBIG * GEO];      // geo out fp16 (4 MB)
__device__ unsigned short g_H1[(size_t)MBIG * DIM];  // fp16, 64 MB
__device__ unsigned short g_H2[(size_t)MBIG * DIM];  // fp16, 64 MB
__device__ unsigned short g_W1[DIM * GEO];       // [N,K] w1 geo slice fp16
__device__ unsigned short g_W2[DIM * DIM];       // [N,K] fp16
__device__ unsigned short g_W3[DIM * DIM];       // [N,K] fp16

// ---------------------------------------------------------------------------
// Helpers (sm_80+ only: cp.async, ldmatrix, mma.sync)
// ---------------------------------------------------------------------------
__device__ __forceinline__ uint32_t smem_u32(const void* p) {
    uint32_t a;
    asm("{ .reg .u64 t; cvta.to.shared.u64 t, %1; cvt.u32.u64 %0, t; }"
        : "=r"(a) : "l"(p));
    return a;
}
__device__ __forceinline__ void cp16(uint32_t dst, const void* src) {
    asm volatile("cp.async.cg.shared.global [%0], [%1], 16;" :: "r"(dst), "l"(src));
}
__device__ __forceinline__ void cp_commit() {
    asm volatile("cp.async.commit_group;" ::: "memory");
}
template<int N> __device__ __forceinline__ void cp_wait() {
    asm volatile("cp.async.wait_group %0;" :: "n"(N) : "memory");
}
#define SWZ128(o) ((o) ^ (((o) >> 3) & 0x70))

__device__ __forceinline__ void ldsm4(uint32_t& r0, uint32_t& r1,
                                      uint32_t& r2, uint32_t& r3, uint32_t addr) {
    asm volatile("ldmatrix.sync.aligned.m8n8.x4.shared.b16 {%0,%1,%2,%3}, [%4];"
                 : "=r"(r0), "=r"(r1), "=r"(r2), "=r"(r3) : "r"(addr));
}
__device__ __forceinline__ void mma_f16(float* c,
                                        const uint32_t* a, const uint32_t* b) {
    asm volatile("mma.sync.aligned.m16n8k16.row.col.f32.f16.f16.f32 "
                 "{%0,%1,%2,%3}, {%4,%5,%6,%7}, {%8,%9}, {%0,%1,%2,%3};"
                 : "+f"(c[0]), "+f"(c[1]), "+f"(c[2]), "+f"(c[3])
                 : "r"(a[0]), "r"(a[1]), "r"(a[2]), "r"(a[3]),
                   "r"(b[0]), "r"(b[1]));
}

__device__ __forceinline__ unsigned short f2h_bits(float v) {
    __half h = __float2half_rn(v);
    return *reinterpret_cast<unsigned short*>(&h);
}

// ---------------------------------------------------------------------------
// fp16 HMMA mainloop: 128x128 CTA tile, 4 warps as 2(M)x2(N), warp tile
// 64x64 (acc 128 regs/thread). K chunk 64 (128B rows, SW128).
// 3-stage cp.async pipeline, 32 KB/stage, 2 CTAs/SM. 128 threads/CTA.
// Issue mix per k-step per warp: 8 ldsm : 32 mma (vs 6:16 before).
// ---------------------------------------------------------------------------
#define KCH 64
#define NKC (DIM / KCH)            // 16
#define STG_BYTES 32768
#define HMMA_SMEM (3 * STG_BYTES + 128)

struct HmmaCtx {
    uint32_t sbase;
    int tid, lane, wm, wn, mtile, ntile;
};

__device__ __forceinline__ void hmma_mainloop(
    const HmmaCtx& c,
    const unsigned short* __restrict__ A,
    const unsigned short* __restrict__ B,
    float acc[4][8][4])
{
#pragma unroll
    for (int mf = 0; mf < 4; mf++)
#pragma unroll
        for (int nf = 0; nf < 8; nf++)
#pragma unroll
            for (int e = 0; e < 4; e++) acc[mf][nf][e] = 0.f;

    auto load_chunk = [&](int kc, int stg) {
        const uint32_t s0 = c.sbase + (uint32_t)stg * STG_BYTES;
#pragma unroll
        for (int it = 0; it < 8; it++) {
            int t = c.tid + (it << 7);
            int rr = t >> 3, ss = t & 7;
            cp16(s0 + SWZ128((uint32_t)(rr * 128 + ss * 16)),
                 A + (size_t)((c.mtile << 7) + rr) * DIM + kc * KCH + ss * 8);
        }
#pragma unroll
        for (int it = 0; it < 8; it++) {
            int t = c.tid + (it << 7);
            int rr = t >> 3, ss = t & 7;
            cp16(s0 + 16384u + SWZ128((uint32_t)(rr * 128 + ss * 16)),
                 B + (size_t)((c.ntile << 7) + rr) * DIM + kc * KCH + ss * 8);
        }
        cp_commit();
    };

    const int a_rl = c.lane & 15;
    const int a_cl = (c.lane >> 4) << 3;
    const int b_rl = (c.lane & 7) + ((c.lane >> 4) << 3);
    const int b_cl = ((c.lane >> 3) & 1) << 3;

    auto compute = [&](int stg) {
        const uint32_t s0 = c.sbase + (uint32_t)stg * STG_BYTES;
        const uint32_t sA = s0, sB = s0 + 16384u;
#pragma unroll
        for (int ks = 0; ks < 4; ks++) {
            const int k0 = ks * 16;
            uint32_t bf[8][2];
#pragma unroll
            for (int np = 0; np < 4; np++) {
                const int n0 = c.wn * 64 + np * 16;
                const uint32_t off =
                    SWZ128((uint32_t)((n0 + b_rl) * 128 + (k0 + b_cl) * 2));
                uint32_t r0, r1, r2, r3;
                ldsm4(r0, r1, r2, r3, sB + off);
                bf[np * 2][0] = r0; bf[np * 2][1] = r1;
                bf[np * 2 + 1][0] = r2; bf[np * 2 + 1][1] = r3;
            }
            uint32_t af[4][4];
#pragma unroll
            for (int mf = 0; mf < 4; mf++) {
                const int m0 = c.wm * 64 + mf * 16;
                const uint32_t off =
                    SWZ128((uint32_t)((m0 + a_rl) * 128 + (k0 + a_cl) * 2));
                ldsm4(af[mf][0], af[mf][1], af[mf][2], af[mf][3], sA + off);
            }
#pragma unroll
            for (int mf = 0; mf < 4; mf++)
#pragma unroll
                for (int nf = 0; nf < 8; nf++)
                    mma_f16(acc[mf][nf], af[mf], bf[nf]);
        }
    };

    load_chunk(0, 0);
    load_chunk(1, 1);
    for (int kc = 0; kc < NKC; kc++) {
        if (kc + 2 < NKC) {
            load_chunk(kc + 2, (kc + 2) % 3);
            cp_wait<2>();
        } else if (kc + 1 < NKC) {
            cp_wait<1>();
        } else {
            cp_wait<0>();
        }
        __syncthreads();
        compute(kc % 3);
        __syncthreads();
    }
}

// Layer 2: out = relu(A @ B^T + bias) -> fp16
__global__ void __launch_bounds__(128, 2)
hmma_l2_kernel(const unsigned short* __restrict__ A,
               const unsigned short* __restrict__ B,
               const float* __restrict__ bias,
               unsigned short* __restrict__ outH)
{
    extern __shared__ char smem_raw[];
    HmmaCtx c;
    c.sbase = (smem_u32(smem_raw) + 127u) & ~127u;
    c.tid = threadIdx.x;
    c.lane = c.tid & 31;
    const int w = c.tid >> 5;
    c.wm = w >> 1; c.wn = w & 1;
    c.mtile = blockIdx.y; c.ntile = blockIdx.x;

    float acc[4][8][4];
    hmma_mainloop(c, A, B, acc);

    const int rl = c.lane >> 2;
    const int cl = (c.lane & 3) << 1;
#pragma unroll
    for (int mf = 0; mf < 4; mf++) {
        const int m_base = (c.mtile << 7) + c.wm * 64 + mf * 16 + rl;
#pragma unroll
        for (int nf = 0; nf < 8; nf++) {
            const int n = (c.ntile << 7) + c.wn * 64 + nf * 8 + cl;
            const float b0 = bias[n], b1 = bias[n + 1];
#pragma unroll
            for (int half = 0; half < 2; half++) {
                const int m = m_base + half * 8;
                float v0 = fmaxf(acc[mf][nf][half * 2 + 0] + b0, 0.f);
                float v1 = fmaxf(acc[mf][nf][half * 2 + 1] + b1, 0.f);
                *(uint32_t*)(outH + (size_t)m * DIM + n) =
                    (uint32_t)f2h_bits(v0) | ((uint32_t)f2h_bits(v1) << 16);
            }
        }
    }
}

// Layer 3 fused with top-18-sum. The CTA M-tile (128 rows) is exactly the
// full j-range of one (b,i): topk is CTA-local. Stage the fp32 tile in the
// reused pipeline smem [128][TPAD]; 128 threads, one per column, scan 128
// rows each and write T directly. No HA buffer, no topk kernel.
#define TPAD 132

__global__ void __launch_bounds__(128, 2)
hmma_l3_topk_kernel(const unsigned short* __restrict__ A,
                    const unsigned short* __restrict__ B,
                    const float* __restrict__ bias,
                    float* __restrict__ T)
{
    extern __shared__ char smem_raw[];
    HmmaCtx c;
    c.sbase = (smem_u32(smem_raw) + 127u) & ~127u;
    c.tid = threadIdx.x;
    c.lane = c.tid & 31;
    const int w = c.tid >> 5;
    c.wm = w >> 1; c.wn = w & 1;
    c.mtile = blockIdx.y; c.ntile = blockIdx.x;

    float acc[4][8][4];
    hmma_mainloop(c, A, B, acc);

    // stage fp32 tile [128 rows(j)][128 cols] in smem (reuse pipeline space)
    char* sm_c = smem_raw + (c.sbase - smem_u32(smem_raw));
    float* smf = (float*)sm_c;
    const int rl = c.lane >> 2;
    const int cl = (c.lane & 3) << 1;
#pragma unroll
    for (int mf = 0; mf < 4; mf++) {
        const int ml_base = c.wm * 64 + mf * 16 + rl;
#pragma unroll
        for (int nf = 0; nf < 8; nf++) {
            const int nl = c.wn * 64 + nf * 8 + cl;
            const int n = (c.ntile << 7) + nl;
            const float b0 = bias[n], b1 = bias[n + 1];
#pragma unroll
            for (int half = 0; half < 2; half++) {
                const int ml = ml_base + half * 8;
                smf[ml * TPAD + nl] = acc[mf][nf][half * 2 + 0] + b0;
                smf[ml * TPAD + nl + 1] = acc[mf][nf][half * 2 + 1] + b1;
            }
        }
    }
    __syncthreads();

    // one thread per column: top-18 insertion over the 128 rows
    const int cidx = c.tid;
    float t18[TOPK];
#pragma unroll
    for (int s = 0; s < TOPK; s++) t18[s] = -3.4e38f;
    for (int j = 0; j < NP; j++) {
        float v = smf[j * TPAD + cidx];
        if (v > t18[TOPK - 1]) {
            t18[TOPK - 1] = v;
#pragma unroll
            for (int s = TOPK - 1; s > 0; s--) {
                if (t18[s] > t18[s - 1]) {
                    float tmp = t18[s - 1]; t18[s - 1] = t18[s]; t18[s] = tmp;
                }
            }
        }
    }
    float sum = 0.f;
#pragma unroll
    for (int s = 0; s < TOPK; s++) sum += t18[s];
    T[(size_t)c.mtile * DIM + (c.ntile << 7) + cidx] = sum * 0.125f;
}

// ---------------------------------------------------------------------------
// Layer-1 fp16 HMMA (K=64): H1 = relu( G3 @ W1g^T + FA_j + FB_i + b1 )
// ---------------------------------------------------------------------------
#define L1_SMEM (2 * 16384 + 128)

__global__ void __launch_bounds__(256, 3)
hmma_l1_kernel(const unsigned short* __restrict__ A,   // G3 fp16 [MBIG, 64]
               const unsigned short* __restrict__ B,   // W1g fp16 [1024, 64]
               const float* __restrict__ bias,
               const float* __restrict__ FA,
               const float* __restrict__ FB,
               unsigned short* __restrict__ outH)
{
    extern __shared__ char smem_raw[];
    const uint32_t sbase = (smem_u32(smem_raw) + 127u) & ~127u;
    const int tid = threadIdx.x;
    const int mtile = blockIdx.y, ntile = blockIdx.x;
    const int lane = tid & 31;
    const int w = tid >> 5;
    const int wm = w >> 2;
    const int wn = w & 3;

#pragma unroll
    for (int it = 0; it < 4; it++) {
        int t = tid + (it << 8);
        int rr = t >> 3, ss = t & 7;
        cp16(sbase + SWZ128((uint32_t)(rr * 128 + ss * 16)),
             A + (size_t)((mtile << 7) + rr) * GEO + ss * 8);
    }
#pragma unroll
    for (int it = 0; it < 4; it++) {
        int t = tid + (it << 8);
        int rr = t >> 3, ss = t & 7;
        cp16(sbase + 16384u + SWZ128((uint32_t)(rr * 128 + ss * 16)),
             B + (size_t)((ntile << 7) + rr) * GEO + ss * 8);
    }
    cp_commit();

    float acc[4][4][4];
#pragma unroll
    for (int mf = 0; mf < 4; mf++)
#pragma unroll
        for (int nf = 0; nf < 4; nf++)
#pragma unroll
            for (int e = 0; e < 4; e++) acc[mf][nf][e] = 0.f;

    const int a_rl = lane & 15;
    const int a_cl = (lane >> 4) << 3;
    const int b_rl = (lane & 7) + ((lane >> 4) << 3);
    const int b_cl = ((lane >> 3) & 1) << 3;

    cp_wait<0>();
    __syncthreads();

    const uint32_t sA = sbase, sB = sbase + 16384u;
#pragma unroll
    for (int ks = 0; ks < 4; ks++) {
        const int k0 = ks * 16;
        uint32_t bf[4][2];
#pragma unroll
        for (int np = 0; np < 2; np++) {
            const int n0 = wn * 32 + np * 16;
            const uint32_t off =
                SWZ128((uint32_t)((n0 + b_rl) * 128 + (k0 + b_cl) * 2));
            uint32_t r0, r1, r2, r3;
            ldsm4(r0, r1, r2, r3, sB + off);
            bf[np * 2][0] = r0; bf[np * 2][1] = r1;
            bf[np * 2 + 1][0] = r2; bf[np * 2 + 1][1] = r3;
        }
        uint32_t af[4][4];
#pragma unroll
        for (int mf = 0; mf < 4; mf++) {
            const int m0 = wm * 64 + mf * 16;
            const uint32_t off =
                SWZ128((uint32_t)((m0 + a_rl) * 128 + (k0 + a_cl) * 2));
            ldsm4(af[mf][0], af[mf][1], af[mf][2], af[mf][3], sA + off);
        }
#pragma unroll
        for (int mf = 0; mf < 4; mf++)
#pragma unroll
            for (int nf = 0; nf < 4; nf++)
                mma_f16(acc[mf][nf], af[mf], bf[nf]);
    }

    const int rl = lane >> 2;
    const int cl = (lane & 3) << 1;
#pragma unroll
    for (int mf = 0; mf < 4; mf++) {
        const int m_base = (mtile << 7) + wm * 64 + mf * 16 + rl;
#pragma unroll
        for (int nf = 0; nf < 4; nf++) {
            const int n = (ntile << 7) + wn * 32 + nf * 8 + cl;
            const float b0 = bias[n], b1 = bias[n + 1];
#pragma unroll
            for (int half = 0; half < 2; half++) {
                const int m = m_base + half * 8;
                const int j = m & (NP - 1);
                const int bi = m >> 7;
                const int bb = bi >> 7;
                const float* aJ = FA + (size_t)((bb << 7) + j) * DIM;
                const float* aI = FB + (size_t)bi * DIM;
                float v0 = acc[mf][nf][half * 2 + 0] + b0 + aJ[n] + aI[n];
                float v1 = acc[mf][nf][half * 2 + 1] + b1 + aJ[n + 1] + aI[n + 1];
                v0 = fmaxf(v0, 0.f); v1 = fmaxf(v1, 0.f);
                *(uint32_t*)(outH + (size_t)m * DIM + n) =
                    (uint32_t)f2h_bits(v0) | ((uint32_t)f2h_bits(v1) << 16);
            }
        }
    }
}

// ---------------------------------------------------------------------------
// Split-K SGEMM for small-M GEMMs (single-B and dual-B variants)
// ---------------------------------------------------------------------------
#define SKM 64
#define SKN 128

__device__ __forceinline__ void splitk_body(
    const float* __restrict__ A, const float* __restrict__ B,
    float* __restrict__ P, int M, int N, int K, int KSL, int slice, int pslice)
{
    __shared__ float As[16][SKM + 4];
    __shared__ float Bs[16][SKN];

    const int bm = blockIdx.y * SKM;
    const int bn = blockIdx.x * SKN;
    const int tid = threadIdx.x;
    const int arow = tid >> 2, acol = (tid & 3) << 2;
    const int brow = tid >> 5, bcol = (tid & 31) << 2;
    const int tx = tid & 31;
    const int ty = tid >> 5;

    float acc[8][4];
#pragma unroll
    for (int a = 0; a < 8; a++)
#pragma unroll
        for (int b = 0; b < 4; b++) acc[a][b] = 0.f;

    const float* Aptr = A + (size_t)(bm + arow) * K + slice * KSL + acol;
    const float* Bptr = B + (size_t)(slice * KSL + brow) * N + bn + bcol;

    for (int k0 = 0; k0 < KSL; k0 += 16) {
        float4 a0 = *(const float4*)(Aptr + k0);
        float4 b0 = *(const float4*)(Bptr + (size_t)k0 * N);
        float4 b1 = *(const float4*)(Bptr + (size_t)(k0 + 8) * N);
        __syncthreads();
        As[acol + 0][arow] = a0.x; As[acol + 1][arow] = a0.y;
        As[acol + 2][arow] = a0.z; As[acol + 3][arow] = a0.w;
        *(float4*)&Bs[brow][bcol] = b0;
        *(float4*)&Bs[brow + 8][bcol] = b1;
        __syncthreads();
#pragma unroll
        for (int kk = 0; kk < 16; kk++) {
            float ra[8], rb[4];
#pragma unroll
            for (int a = 0; a < 8; a++) ra[a] = As[kk][ty * 8 + a];
#pragma unroll
            for (int b = 0; b < 4; b++) rb[b] = Bs[kk][tx * 4 + b];
#pragma unroll
            for (int a = 0; a < 8; a++)
#pragma unroll
                for (int b = 0; b < 4; b++)
                    acc[a][b] = fmaf(ra[a], rb[b], acc[a][b]);
        }
    }

    float* Pp = P + (size_t)pslice * M * N;
#pragma unroll
    for (int a = 0; a < 8; a++) {
        int m = bm + ty * 8 + a;
        float4 v;
        v.x = acc[a][0]; v.y = acc[a][1]; v.z = acc[a][2]; v.w = acc[a][3];
        *(float4*)(Pp + (size_t)m * N + bn + tx * 4) = v;
    }
}

__global__ __launch_bounds__(256)
void sgemm_splitk(const float* __restrict__ A, const float* __restrict__ B,
                  float* __restrict__ P, int M, int N, int K, int KSL)
{
    splitk_body(A, B, P, M, N, K, KSL, blockIdx.z, blockIdx.z);
}

// dual-B: z < NS uses B0 (P slice z), else B1 (P slice z)
__global__ __launch_bounds__(256)
void sgemm_splitk_dual(const float* __restrict__ A,
                       const float* __restrict__ B0,
                       const float* __restrict__ B1,
                       float* __restrict__ P, int M, int N, int K, int KSL,
                       int NS)
{
    const int z = blockIdx.z;
    const float* B = (z < NS) ? B0 : B1;
    splitk_body(A, B, P, M, N, K, KSL, (z < NS) ? z : z - NS, z);
}

__global__ __launch_bounds__(256)
void skreduce(const float* __restrict__ P, int nsl,
              const float* __restrict__ bias, int relu,
              float* __restrict__ C, int MN, int N)
{
    int idx = blockIdx.x * blockDim.x + threadIdx.x;
    if (idx >= MN) return;
    float s = 0.f;
    for (int sl = 0; sl < nsl; sl++) s += P[(size_t)sl * MN + idx];
    if (bias) s += bias[idx % N];
    if (relu) s = fmaxf(s, 0.f);
    C[idx] = s;
}

// dual reduce: first MN -> C0 (slices 0..nsl), second MN -> C1 (slices nsl..2nsl)
__global__ __launch_bounds__(256)
void skreduce_dual(const float* __restrict__ P, int nsl,
                   float* __restrict__ C0, float* __restrict__ C1, int MN)
{
    int idx = blockIdx.x * blockDim.x + threadIdx.x;
    int which = idx >= MN;
    int base = which ? nsl : 0;
    int off = which ? idx - MN : idx;
    float s = 0.f;
    for (int sl = 0; sl < nsl; sl++)
        s += P[(size_t)(base + sl) * MN + off];
    if (which) C1[off] = s; else C0[off] = s;
}

// ---------------------------------------------------------------------------
// Weight transpose + fp16 convert:  W[Kd, Nd] -> Wh [Nd, Kd]
// ---------------------------------------------------------------------------
__global__ void wsplit_kernel(const float* __restrict__ W,
                              unsigned short* __restrict__ Wh,
                              int Kd, int Nd)
{
    __shared__ float tile[32][33];
    const int n0 = blockIdx.x * 32, k0 = blockIdx.y * 32;
    const int tx = threadIdx.x, ty = threadIdx.y;   // 32 x 8
#pragma unroll
    for (int i = 0; i < 32; i += 8)
        tile[ty + i][tx] = W[(size_t)(k0 + ty + i) * Nd + n0 + tx];
    __syncthreads();
#pragma unroll
    for (int i = 0; i < 32; i += 8) {
        Wh[(size_t)(n0 + ty + i) * Kd + k0 + tx] = f2h_bits(tile[tx][ty + i]);
    }
}

// ---------------------------------------------------------------------------
// Geo embedding + 3-layer 64-wide MLP (fused) -> fp16 output
// ---------------------------------------------------------------------------
__global__ __launch_bounds__(128)
void geo_kernel(const float* __restrict__ prop,
                const float* __restrict__ w1, const float* __restrict__ b1,
                const float* __restrict__ w2, const float* __restrict__ b2,
                const float* __restrict__ w3, const float* __restrict__ b3,
                unsigned short* __restrict__ G3)
{
    __shared__ float sw1[GEO * GEO], sw2[GEO * GEO], sw3[GEO * GEO];
    __shared__ float sb1[GEO], sb2[GEO], sb3[GEO];
    __shared__ float esm[128 * 65];

    const int tid = threadIdx.x;
    for (int t = tid; t < GEO * GEO; t += blockDim.x) {
        sw1[t] = w1[t]; sw2[t] = w2[t]; sw3[t] = w3[t];
    }
    for (int t = tid; t < GEO; t += blockDim.x) {
        sb1[t] = b1[t]; sb2[t] = b2[t]; sb3[t] = b3[t];
    }
    __syncthreads();

    const int row = blockIdx.x * blockDim.x + tid;
    const int b = row >> 14;
    const int i = (row >> 7) & (NP - 1);
    const int j = row & (NP - 1);

    const float* pi = prop + ((size_t)(b * NP + i)) * 4;
    const float* pj = prop + ((size_t)(b * NP + j)) * 4;
    float wi = pi[2] - pi[0] + 1.f, hi = pi[3] - pi[1] + 1.f;
    float wj = pj[2] - pj[0] + 1.f, hj = pj[3] - pj[1] + 1.f;
    float cxi = 0.5f * (pi[0] + pi[2]), cyi = 0.5f * (pi[1] + pi[3]);
    float cxj = 0.5f * (pj[0] + pj[2]), cyj = 0.5f * (pj[1] + pj[3]);

    float pos[4];
    pos[0] = (cxi - cxj) / wj;
    pos[1] = (cyi - cyj) / hj;
    pos[2] = wi / wj;
    pos[3] = hi / hj;

    const float dm[8] = {1.0f, 2.3713737f, 5.6234133f, 13.335215f,
                         31.622777f, 74.989421f, 177.82794f, 421.69650f};

    float* my = &esm[tid * 65];
#pragma unroll
    for (int p = 0; p < 4; p++) {
        float lp = logf(fmaxf(fabsf(pos[p]), 1e-3f)) * 100.f;
#pragma unroll
        for (int r = 0; r < 8; r++) {
            float arg = lp / dm[r];
            float s, c;
            sincosf(arg, &s, &c);
            my[p * 16 + r] = s;
            my[p * 16 + 8 + r] = c;
        }
    }

    float acc[GEO];
#pragma unroll
    for (int o = 0; o < GEO; o++) acc[o] = sb1[o];
    for (int k = 0; k < GEO; k++) {
        float ek = my[k];
        const float* wr = &sw1[k * GEO];
#pragma unroll
        for (int o = 0; o < GEO; o++) acc[o] = fmaf(ek, wr[o], acc[o]);
    }
#pragma unroll
    for (int o = 0; o < GEO; o++) my[o] = fmaxf(acc[o], 0.f);

#pragma unroll
    for (int o = 0; o < GEO; o++) acc[o] = sb2[o];
    for (int k = 0; k < GEO; k++) {
        float ek = my[k];
        const float* wr = &sw2[k * GEO];
#pragma unroll
        for (int o = 0; o < GEO; o++) acc[o] = fmaf(ek, wr[o], acc[o]);
    }
#pragma unroll
    for (int o = 0; o < GEO; o++) my[o] = fmaxf(acc[o], 0.f);

#pragma unroll
    for (int o = 0; o < GEO; o++) acc[o] = sb3[o];
    for (int k = 0; k < GEO; k++) {
        float ek = my[k];
        const float* wr = &sw3[k * GEO];
#pragma unroll
        for (int o = 0; o < GEO; o++) acc[o] = fmaf(ek, wr[o], acc[o]);
    }
    unsigned short* outp = G3 + (size_t)row * GEO;
#pragma unroll
    for (int o = 0; o < GEO; o++) outp[o] = f2h_bits(acc[o]);
}

// ---------------------------------------------------------------------------
// concat + heads
// ---------------------------------------------------------------------------
__global__ void cat_kernel(const float* __restrict__ feats,
                           const float* __restrict__ T,
                           float* __restrict__ CAT)
{
    int idx = blockIdx.x * blockDim.x + threadIdx.x;
    int m = idx >> 11;
    int k = idx & 2047;
    float v = (k < DIM) ? feats[(size_t)m * DIM + k]
                        : T[(size_t)m * DIM + (k - DIM)];
    CAT[idx] = v;
}

__global__ __launch_bounds__(128)
void heads_kernel(const float* __restrict__ X,
                  const float* __restrict__ subject,
                  const float* __restrict__ obj,
                  const float* __restrict__ cs_w, const float* __restrict__ cs_b,
                  const float* __restrict__ cso_w, const float* __restrict__ cso_b,
                  float* __restrict__ out)
{
    int row = blockIdx.x;
    int b = row >> 7;
    int tid = threadIdx.x;

    float as = 0.f, ao = 0.f;
    for (int k = tid; k < DIM; k += 128) {
        float xv = X[(size_t)row * DIM + k];
        float sv = subject[(size_t)b * DIM + k];
        float ov = obj[(size_t)b * DIM + k];
        as += xv * cs_w[k] + sv * cs_w[DIM + k];
        ao += xv * cso_w[k] + ov * cso_w[DIM + k];
    }
    __shared__ float rs[128], ro[128];
    rs[tid] = as; ro[tid] = ao;
    __syncthreads();
    for (int s = 64; s > 0; s >>= 1) {
        if (tid < s) { rs[tid] += rs[tid + s]; ro[tid] += ro[tid + s]; }
        __syncthreads();
    }
    if (tid == 0) {
        float s1 = rs[0] + cs_b[0];
        float s2 = ro[0] + cso_b[0];
        out[row * 2 + 0] = 1.f / (1.f + expf(-s1));
        out[row * 2 + 1] = 1.f / (1.f + expf(-s2));
    }
}

// ---------------------------------------------------------------------------
// Launch
// ---------------------------------------------------------------------------
extern "C" void kernel_launch(void* const* d_in, const int* in_sizes, int n_in,
                              void* d_out, int out_size)
{
    const float* feats   = (const float*)d_in[0];
    const float* subject = (const float*)d_in[1];
    const float* obj     = (const float*)d_in[2];
    const float* prop    = (const float*)d_in[3];
    const float* gp_w1 = (const float*)d_in[4];
    const float* gp_b1 = (const float*)d_in[5];
    const float* gp_w2 = (const float*)d_in[6];
    const float* gp_b2 = (const float*)d_in[7];
    const float* gp_w3 = (const float*)d_in[8];
    const float* gp_b3 = (const float*)d_in[9];
    const float* pm_w1 = (const float*)d_in[10];
    const float* pm_b1 = (const float*)d_in[11];
    const float* pm_w2 = (const float*)d_in[12];
    const float* pm_b2 = (const float*)d_in[13];
    const float* pm_w3 = (const float*)d_in[14];
    const float* pm_b3 = (const float*)d_in[15];
    const float* ag_w1 = (const float*)d_in[16];
    const float* ag_b1 = (const float*)d_in[17];
    const float* ag_w2 = (const float*)d_in[18];
    const float* ag_b2 = (const float*)d_in[19];
    const float* ag_w3 = (const float*)d_in[20];
    const float* ag_b3 = (const float*)d_in[21];
    const float* cs_w  = (const float*)d_in[22];
    const float* cs_b  = (const float*)d_in[23];
    const float* cso_w = (const float*)d_in[24];
    const float* cso_b = (const float*)d_in[25];
    float* out = (float*)d_out;

    float *FA, *FB, *T, *CAT, *SA, *SB, *P;
    unsigned short *G3, *H1, *H2, *W1, *W2, *W3;
    cudaGetSymbolAddress((void**)&FA, g_FA);
    cudaGetSymbolAddress((void**)&FB, g_FB);
    cudaGetSymbolAddress((void**)&T,  g_T);
    cudaGetSymbolAddress((void**)&CAT, g_CAT);
    cudaGetSymbolAddress((void**)&SA, g_SA);
    cudaGetSymbolAddress((void**)&SB, g_SB);
    cudaGetSymbolAddress((void**)&P,  g_P);
    cudaGetSymbolAddress((void**)&G3, g_G3);
    cudaGetSymbolAddress((void**)&H1, g_H1);
    cudaGetSymbolAddress((void**)&H2, g_H2);
    cudaGetSymbolAddress((void**)&W1, g_W1);
    cudaGetSymbolAddress((void**)&W2, g_W2);
    cudaGetSymbolAddress((void**)&W3, g_W3);

    cudaFuncSetAttribute(hmma_l2_kernel,
                         cudaFuncAttributeMaxDynamicSharedMemorySize, HMMA_SMEM);
    cudaFuncSetAttribute(hmma_l3_topk_kernel,
                         cudaFuncAttributeMaxDynamicSharedMemorySize, HMMA_SMEM);
    cudaFuncSetAttribute(hmma_l1_kernel,
                         cudaFuncAttributeMaxDynamicSharedMemorySize, L1_SMEM);

    dim3 ghm(DIM / 128, MBIG / 128);          // (8, 256)
    dim3 gws(DIM / 32, DIM / 32);
    dim3 gws1(DIM / 32, GEO / 32);
    const int MN = MSMALL * DIM;              // 262144

    // Weight transpose + fp16 convert (tiny)
    wsplit_kernel<<<gws, dim3(32, 8)>>>(pm_w2, W2, DIM, DIM);
    wsplit_kernel<<<gws, dim3(32, 8)>>>(pm_w3, W3, DIM, DIM);
    wsplit_kernel<<<gws1, dim3(32, 8)>>>(pm_w1 + (size_t)2 * DIM * DIM,
                                         W1, GEO, DIM);

    // FA & FB in one dual split-K launch (K=1024, 16 slices each)
    dim3 gskd(DIM / SKN, MSMALL / SKM, 32);   // 1024 CTAs
    sgemm_splitk_dual<<<gskd, 256>>>(feats, pm_w1, pm_w1 + (size_t)DIM * DIM,
                                     P, MSMALL, DIM, DIM, 64, 16);
    skreduce_dual<<<(2 * MN) / 256, 256>>>(P, 16, FA, FB, MN);

    // Geo embedding + geo MLP -> fp16
    geo_kernel<<<MBIG / 128, 128>>>(prop, gp_w1, gp_b1, gp_w2, gp_b2,
                                    gp_w3, gp_b3, G3);

    // Pairwise layer 1 (fp16 HMMA, K=64) -> H1 fp16
    hmma_l1_kernel<<<ghm, 256, L1_SMEM>>>(G3, W1, pm_b1, FA, FB, H1);

    // Pairwise layer 2 (fp16 HMMA, 64x64 warp tile) -> H2 fp16, relu
    hmma_l2_kernel<<<ghm, 128, HMMA_SMEM>>>(H1, W2, pm_b2, H2);
    // Pairwise layer 3 + fused top-18 sum -> T directly
    hmma_l3_topk_kernel<<<ghm, 128, HMMA_SMEM>>>(H2, W3, pm_b3, T);

    // Aggregate MLP via split-K
    cat_kernel<<<(MSMALL * 2 * DIM) / 256, 256>>>(feats, T, CAT);
    dim3 gsk(DIM / SKN, MSMALL / SKM, 16);
    dim3 gsk32(DIM / SKN, MSMALL / SKM, 32);  // K=2048, 32 slices
    sgemm_splitk<<<gsk32, 256>>>(CAT, ag_w1, P, MSMALL, DIM, 2 * DIM, 64);
    skreduce<<<MN / 256, 256>>>(P, 32, ag_b1, 1, SA, MN, DIM);
    sgemm_splitk<<<gsk, 256>>>(SA, ag_w2, P, MSMALL, DIM, DIM, 64);
    skreduce<<<MN / 256, 256>>>(P, 16, ag_b2, 1, SB, MN, DIM);
    sgemm_splitk<<<gsk, 256>>>(SB, ag_w3, P, MSMALL, DIM, DIM, 64);
    skreduce<<<MN / 256, 256>>>(P, 16, ag_b3, 0, SA, MN, DIM);

    // Heads
    heads_kernel<<<MSMALL, 128>>>(SA, subject, obj, cs_w, cs_b, cso_w, cso_b, out);
}

// round 9
// speedup vs baseline: 1.0351x; 1.0351x over previous
#include <cuda_runtime.h>
#include <cuda_fp16.h>
#include <cstdint>
#include <cstddef>

// ---------------------------------------------------------------------------
// Problem constants
// ---------------------------------------------------------------------------
#define BSZ 2
#define NP  128
#define DIM 1024
#define GEO 64
#define TOPK 18
#define MBIG (BSZ * NP * NP)     // 32768 pairwise rows
#define MSMALL (BSZ * NP)        // 256 proposal rows

// ---------------------------------------------------------------------------
// Scratch (static device globals)
// ---------------------------------------------------------------------------
__device__ float g_FA[MSMALL * DIM];
__device__ float g_FB[MSMALL * DIM];
__device__ float g_T[MSMALL * DIM];
__device__ float g_SA[MSMALL * DIM];
__device__ float g_SB[MSMALL * DIM];
__device__ float g_P[32 * MSMALL * DIM];         // split-K partials (32 MB)
__device__ unsigned short g_G3[MBIG * GEO];      // geo out fp16 (4 MB)
__device__ unsigned short g_H1[(size_t)MBIG * DIM];  // fp16, 64 MB
__device__ unsigned short g_H2[(size_t)MBIG * DIM];  // fp16, 64 MB
__device__ unsigned short g_W1[DIM * GEO];       // [N,K] w1 geo slice fp16
__device__ unsigned short g_W2[DIM * DIM];       // [N,K] fp16
__device__ unsigned short g_W3[DIM * DIM];       // [N,K] fp16

// ---------------------------------------------------------------------------
// Helpers (sm_80+ only: cp.async, ldmatrix, mma.sync)
// ---------------------------------------------------------------------------
__device__ __forceinline__ uint32_t smem_u32(const void* p) {
    uint32_t a;
    asm("{ .reg .u64 t; cvta.to.shared.u64 t, %1; cvt.u32.u64 %0, t; }"
        : "=r"(a) : "l"(p));
    return a;
}
__device__ __forceinline__ void cp16(uint32_t dst, const void* src) {
    asm volatile("cp.async.cg.shared.global [%0], [%1], 16;" :: "r"(dst), "l"(src));
}
__device__ __forceinline__ void cp_commit() {
    asm volatile("cp.async.commit_group;" ::: "memory");
}
template<int N> __device__ __forceinline__ void cp_wait() {
    asm volatile("cp.async.wait_group %0;" :: "n"(N) : "memory");
}
#define SWZ128(o) ((o) ^ (((o) >> 3) & 0x70))

__device__ __forceinline__ void ldsm4(uint32_t& r0, uint32_t& r1,
                                      uint32_t& r2, uint32_t& r3, uint32_t addr) {
    asm volatile("ldmatrix.sync.aligned.m8n8.x4.shared.b16 {%0,%1,%2,%3}, [%4];"
                 : "=r"(r0), "=r"(r1), "=r"(r2), "=r"(r3) : "r"(addr));
}
__device__ __forceinline__ void mma_f16(float* c,
                                        const uint32_t* a, const uint32_t* b) {
    asm volatile("mma.sync.aligned.m16n8k16.row.col.f32.f16.f16.f32 "
                 "{%0,%1,%2,%3}, {%4,%5,%6,%7}, {%8,%9}, {%0,%1,%2,%3};"
                 : "+f"(c[0]), "+f"(c[1]), "+f"(c[2]), "+f"(c[3])
                 : "r"(a[0]), "r"(a[1]), "r"(a[2]), "r"(a[3]),
                   "r"(b[0]), "r"(b[1]));
}

__device__ __forceinline__ unsigned short f2h_bits(float v) {
    __half h = __float2half_rn(v);
    return *reinterpret_cast<unsigned short*>(&h);
}

// ---------------------------------------------------------------------------
// fp16 HMMA mainloop (128x128 CTA tile, the proven round-7 config).
// 8 warps 2(M)x4(N); warp tile 64x32. K chunk 64 (128B rows, SW128).
// 3-stage cp.async pipeline, 32 KB/stage, 2 CTAs/SM. 256 threads/CTA.
// ---------------------------------------------------------------------------
#define KCH 64
#define NKC (DIM / KCH)            // 16
#define STG_BYTES 32768
#define HMMA_SMEM (3 * STG_BYTES + 128)

struct HmmaCtx {
    uint32_t sbase;
    int tid, lane, wm, wn, mtile, ntile;
};

__device__ __forceinline__ void hmma_mainloop(
    const HmmaCtx& c,
    const unsigned short* __restrict__ A,
    const unsigned short* __restrict__ B,
    float acc[4][4][4])
{
#pragma unroll
    for (int mf = 0; mf < 4; mf++)
#pragma unroll
        for (int nf = 0; nf < 4; nf++)
#pragma unroll
            for (int e = 0; e < 4; e++) acc[mf][nf][e] = 0.f;

    auto load_chunk = [&](int kc, int stg) {
        const uint32_t s0 = c.sbase + (uint32_t)stg * STG_BYTES;
#pragma unroll
        for (int it = 0; it < 4; it++) {
            int t = c.tid + (it << 8);
            int rr = t >> 3, ss = t & 7;
            cp16(s0 + SWZ128((uint32_t)(rr * 128 + ss * 16)),
                 A + (size_t)((c.mtile << 7) + rr) * DIM + kc * KCH + ss * 8);
        }
#pragma unroll
        for (int it = 0; it < 4; it++) {
            int t = c.tid + (it << 8);
            int rr = t >> 3, ss = t & 7;
            cp16(s0 + 16384u + SWZ128((uint32_t)(rr * 128 + ss * 16)),
                 B + (size_t)((c.ntile << 7) + rr) * DIM + kc * KCH + ss * 8);
        }
        cp_commit();
    };

    const int a_rl = c.lane & 15;
    const int a_cl = (c.lane >> 4) << 3;
    const int b_rl = (c.lane & 7) + ((c.lane >> 4) << 3);
    const int b_cl = ((c.lane >> 3) & 1) << 3;

    auto compute = [&](int stg) {
        const uint32_t s0 = c.sbase + (uint32_t)stg * STG_BYTES;
        const uint32_t sA = s0, sB = s0 + 16384u;
#pragma unroll
        for (int ks = 0; ks < 4; ks++) {
            const int k0 = ks * 16;
            uint32_t bf[4][2];
#pragma unroll
            for (int np = 0; np < 2; np++) {
                const int n0 = c.wn * 32 + np * 16;
                const uint32_t off =
                    SWZ128((uint32_t)((n0 + b_rl) * 128 + (k0 + b_cl) * 2));
                uint32_t r0, r1, r2, r3;
                ldsm4(r0, r1, r2, r3, sB + off);
                bf[np * 2][0] = r0; bf[np * 2][1] = r1;
                bf[np * 2 + 1][0] = r2; bf[np * 2 + 1][1] = r3;
            }
            uint32_t af[4][4];
#pragma unroll
            for (int mf = 0; mf < 4; mf++) {
                const int m0 = c.wm * 64 + mf * 16;
                const uint32_t off =
                    SWZ128((uint32_t)((m0 + a_rl) * 128 + (k0 + a_cl) * 2));
                ldsm4(af[mf][0], af[mf][1], af[mf][2], af[mf][3], sA + off);
            }
#pragma unroll
            for (int mf = 0; mf < 4; mf++)
#pragma unroll
                for (int nf = 0; nf < 4; nf++)
                    mma_f16(acc[mf][nf], af[mf], bf[nf]);
        }
    };

    load_chunk(0, 0);
    load_chunk(1, 1);
    for (int kc = 0; kc < NKC; kc++) {
        if (kc + 2 < NKC) {
            load_chunk(kc + 2, (kc + 2) % 3);
            cp_wait<2>();
        } else if (kc + 1 < NKC) {
            cp_wait<1>();
        } else {
            cp_wait<0>();
        }
        __syncthreads();
        compute(kc % 3);
        __syncthreads();
    }
}

// Layer 2: out = relu(A @ B^T + bias) -> fp16
__global__ void __launch_bounds__(256, 2)
hmma_l2_kernel(const unsigned short* __restrict__ A,
               const unsigned short* __restrict__ B,
               const float* __restrict__ bias,
               unsigned short* __restrict__ outH)
{
    extern __shared__ char smem_raw[];
    HmmaCtx c;
    c.sbase = (smem_u32(smem_raw) + 127u) & ~127u;
    c.tid = threadIdx.x;
    c.lane = c.tid & 31;
    const int w = c.tid >> 5;
    c.wm = w >> 2; c.wn = w & 3;
    c.mtile = blockIdx.y; c.ntile = blockIdx.x;

    float acc[4][4][4];
    hmma_mainloop(c, A, B, acc);

    const int rl = c.lane >> 2;
    const int cl = (c.lane & 3) << 1;
#pragma unroll
    for (int mf = 0; mf < 4; mf++) {
        const int m_base = (c.mtile << 7) + c.wm * 64 + mf * 16 + rl;
#pragma unroll
        for (int nf = 0; nf < 4; nf++) {
            const int n = (c.ntile << 7) + c.wn * 32 + nf * 8 + cl;
            const float b0 = bias[n], b1 = bias[n + 1];
#pragma unroll
            for (int half = 0; half < 2; half++) {
                const int m = m_base + half * 8;
                float v0 = fmaxf(acc[mf][nf][half * 2 + 0] + b0, 0.f);
                float v1 = fmaxf(acc[mf][nf][half * 2 + 1] + b1, 0.f);
                *(uint32_t*)(outH + (size_t)m * DIM + n) =
                    (uint32_t)f2h_bits(v0) | ((uint32_t)f2h_bits(v1) << 16);
            }
        }
    }
}

// Layer 3 fused with top-18-sum. CTA M-tile (128 rows) = full j-range of one
// (b,i): topk is CTA-local. Stage fp32 tile in reused pipeline smem, 256
// threads scan 64 rows each (2 per column), merge pairs, write T directly.
#define TPAD 132
#define L3_LISTS (128 * TPAD * 4)   // byte offset of merge lists in smem

__global__ void __launch_bounds__(256, 2)
hmma_l3_topk_kernel(const unsigned short* __restrict__ A,
                    const unsigned short* __restrict__ B,
                    const float* __restrict__ bias,
                    float* __restrict__ T)
{
    extern __shared__ char smem_raw[];
    HmmaCtx c;
    c.sbase = (smem_u32(smem_raw) + 127u) & ~127u;
    c.tid = threadIdx.x;
    c.lane = c.tid & 31;
    const int w = c.tid >> 5;
    c.wm = w >> 2; c.wn = w & 3;
    c.mtile = blockIdx.y; c.ntile = blockIdx.x;

    float acc[4][4][4];
    hmma_mainloop(c, A, B, acc);

    // stage fp32 tile [128 rows(j)][128 cols] in smem (reuse pipeline space)
    char* sm_c = smem_raw + (c.sbase - smem_u32(smem_raw));
    float* smf = (float*)sm_c;
    const int rl = c.lane >> 2;
    const int cl = (c.lane & 3) << 1;
#pragma unroll
    for (int mf = 0; mf < 4; mf++) {
        const int ml_base = c.wm * 64 + mf * 16 + rl;
#pragma unroll
        for (int nf = 0; nf < 4; nf++) {
            const int nl = c.wn * 32 + nf * 8 + cl;
            const int n = (c.ntile << 7) + nl;
            const float b0 = bias[n], b1 = bias[n + 1];
#pragma unroll
            for (int half = 0; half < 2; half++) {
                const int ml = ml_base + half * 8;
                smf[ml * TPAD + nl] = acc[mf][nf][half * 2 + 0] + b0;
                smf[ml * TPAD + nl + 1] = acc[mf][nf][half * 2 + 1] + b1;
            }
        }
    }
    __syncthreads();

    // two threads per column: thread t handles column t&127, rows half*64..+64
    const int cidx = c.tid & 127;
    const int half = c.tid >> 7;
    float t18[TOPK];
#pragma unroll
    for (int s = 0; s < TOPK; s++) t18[s] = -3.4e38f;
    const float* colp = smf + half * 64 * TPAD + cidx;
    for (int j = 0; j < 64; j++) {
        float v = colp[j * TPAD];
        if (v > t18[TOPK - 1]) {
            t18[TOPK - 1] = v;
#pragma unroll
            for (int s = TOPK - 1; s > 0; s--) {
                if (t18[s] > t18[s - 1]) {
                    float tmp = t18[s - 1]; t18[s - 1] = t18[s]; t18[s] = tmp;
                }
            }
        }
    }
    float* lists = (float*)(sm_c + L3_LISTS);
    if (half == 1) {
#pragma unroll
        for (int s = 0; s < TOPK; s++) lists[cidx * TOPK + s] = t18[s];
    }
    __syncthreads();
    if (half == 0) {
#pragma unroll
        for (int s = 0; s < TOPK; s++) {
            float v = lists[cidx * TOPK + s];
            if (v > t18[TOPK - 1]) {
                t18[TOPK - 1] = v;
#pragma unroll
                for (int q = TOPK - 1; q > 0; q--) {
                    if (t18[q] > t18[q - 1]) {
                        float tmp = t18[q - 1]; t18[q - 1] = t18[q]; t18[q] = tmp;
                    }
                }
            }
        }
        float sum = 0.f;
#pragma unroll
        for (int s = 0; s < TOPK; s++) sum += t18[s];
        T[(size_t)c.mtile * DIM + (c.ntile << 7) + cidx] = sum * 0.125f;
    }
}

// ---------------------------------------------------------------------------
// Layer-1 fp16 HMMA (K=64): H1 = relu( G3 @ W1g^T + FA_j + FB_i + b1 )
// ---------------------------------------------------------------------------
#define L1_SMEM (2 * 16384 + 128)

__global__ void __launch_bounds__(256, 3)
hmma_l1_kernel(const unsigned short* __restrict__ A,   // G3 fp16 [MBIG, 64]
               const unsigned short* __restrict__ B,   // W1g fp16 [1024, 64]
               const float* __restrict__ bias,
               const float* __restrict__ FA,
               const float* __restrict__ FB,
               unsigned short* __restrict__ outH)
{
    extern __shared__ char smem_raw[];
    const uint32_t sbase = (smem_u32(smem_raw) + 127u) & ~127u;
    const int tid = threadIdx.x;
    const int mtile = blockIdx.y, ntile = blockIdx.x;
    const int lane = tid & 31;
    const int w = tid >> 5;
    const int wm = w >> 2;
    const int wn = w & 3;

#pragma unroll
    for (int it = 0; it < 4; it++) {
        int t = tid + (it << 8);
        int rr = t >> 3, ss = t & 7;
        cp16(sbase + SWZ128((uint32_t)(rr * 128 + ss * 16)),
             A + (size_t)((mtile << 7) + rr) * GEO + ss * 8);
    }
#pragma unroll
    for (int it = 0; it < 4; it++) {
        int t = tid + (it << 8);
        int rr = t >> 3, ss = t & 7;
        cp16(sbase + 16384u + SWZ128((uint32_t)(rr * 128 + ss * 16)),
             B + (size_t)((ntile << 7) + rr) * GEO + ss * 8);
    }
    cp_commit();

    float acc[4][4][4];
#pragma unroll
    for (int mf = 0; mf < 4; mf++)
#pragma unroll
        for (int nf = 0; nf < 4; nf++)
#pragma unroll
            for (int e = 0; e < 4; e++) acc[mf][nf][e] = 0.f;

    const int a_rl = lane & 15;
    const int a_cl = (lane >> 4) << 3;
    const int b_rl = (lane & 7) + ((lane >> 4) << 3);
    const int b_cl = ((lane >> 3) & 1) << 3;

    cp_wait<0>();
    __syncthreads();

    const uint32_t sA = sbase, sB = sbase + 16384u;
#pragma unroll
    for (int ks = 0; ks < 4; ks++) {
        const int k0 = ks * 16;
        uint32_t bf[4][2];
#pragma unroll
        for (int np = 0; np < 2; np++) {
            const int n0 = wn * 32 + np * 16;
            const uint32_t off =
                SWZ128((uint32_t)((n0 + b_rl) * 128 + (k0 + b_cl) * 2));
            uint32_t r0, r1, r2, r3;
            ldsm4(r0, r1, r2, r3, sB + off);
            bf[np * 2][0] = r0; bf[np * 2][1] = r1;
            bf[np * 2 + 1][0] = r2; bf[np * 2 + 1][1] = r3;
        }
        uint32_t af[4][4];
#pragma unroll
        for (int mf = 0; mf < 4; mf++) {
            const int m0 = wm * 64 + mf * 16;
            const uint32_t off =
                SWZ128((uint32_t)((m0 + a_rl) * 128 + (k0 + a_cl) * 2));
            ldsm4(af[mf][0], af[mf][1], af[mf][2], af[mf][3], sA + off);
        }
#pragma unroll
        for (int mf = 0; mf < 4; mf++)
#pragma unroll
            for (int nf = 0; nf < 4; nf++)
                mma_f16(acc[mf][nf], af[mf], bf[nf]);
    }

    const int rl = lane >> 2;
    const int cl = (lane & 3) << 1;
#pragma unroll
    for (int mf = 0; mf < 4; mf++) {
        const int m_base = (mtile << 7) + wm * 64 + mf * 16 + rl;
#pragma unroll
        for (int nf = 0; nf < 4; nf++) {
            const int n = (ntile << 7) + wn * 32 + nf * 8 + cl;
            const float b0 = bias[n], b1 = bias[n + 1];
#pragma unroll
            for (int half = 0; half < 2; half++) {
                const int m = m_base + half * 8;
                const int j = m & (NP - 1);
                const int bi = m >> 7;
                const int bb = bi >> 7;
                const float* aJ = FA + (size_t)((bb << 7) + j) * DIM;
                const float* aI = FB + (size_t)bi * DIM;
                float v0 = acc[mf][nf][half * 2 + 0] + b0 + aJ[n] + aI[n];
                float v1 = acc[mf][nf][half * 2 + 1] + b1 + aJ[n + 1] + aI[n + 1];
                v0 = fmaxf(v0, 0.f); v1 = fmaxf(v1, 0.f);
                *(uint32_t*)(outH + (size_t)m * DIM + n) =
                    (uint32_t)f2h_bits(v0) | ((uint32_t)f2h_bits(v1) << 16);
            }
        }
    }
}

// ---------------------------------------------------------------------------
// Split-K SGEMM for small-M GEMMs (aslice for A, bslice for B, pslice for P)
// ---------------------------------------------------------------------------
#define SKM 64
#define SKN 128

__device__ __forceinline__ void splitk_body(
    const float* __restrict__ A, const float* __restrict__ B,
    float* __restrict__ P, int M, int N, int K, int KSL,
    int aslice, int bslice, int pslice)
{
    __shared__ float As[16][SKM + 4];
    __shared__ float Bs[16][SKN];

    const int bm = blockIdx.y * SKM;
    const int bn = blockIdx.x * SKN;
    const int tid = threadIdx.x;
    const int arow = tid >> 2, acol = (tid & 3) << 2;
    const int brow = tid >> 5, bcol = (tid & 31) << 2;
    const int tx = tid & 31;
    const int ty = tid >> 5;

    float acc[8][4];
#pragma unroll
    for (int a = 0; a < 8; a++)
#pragma unroll
        for (int b = 0; b < 4; b++) acc[a][b] = 0.f;

    const float* Aptr = A + (size_t)(bm + arow) * K + aslice * KSL + acol;
    const float* Bptr = B + (size_t)(bslice * KSL + brow) * N + bn + bcol;

    for (int k0 = 0; k0 < KSL; k0 += 16) {
        float4 a0 = *(const float4*)(Aptr + k0);
        float4 b0 = *(const float4*)(Bptr + (size_t)k0 * N);
        float4 b1 = *(const float4*)(Bptr + (size_t)(k0 + 8) * N);
        __syncthreads();
        As[acol + 0][arow] = a0.x; As[acol + 1][arow] = a0.y;
        As[acol + 2][arow] = a0.z; As[acol + 3][arow] = a0.w;
        *(float4*)&Bs[brow][bcol] = b0;
        *(float4*)&Bs[brow + 8][bcol] = b1;
        __syncthreads();
#pragma unroll
        for (int kk = 0; kk < 16; kk++) {
            float ra[8], rb[4];
#pragma unroll
            for (int a = 0; a < 8; a++) ra[a] = As[kk][ty * 8 + a];
#pragma unroll
            for (int b = 0; b < 4; b++) rb[b] = Bs[kk][tx * 4 + b];
#pragma unroll
            for (int a = 0; a < 8; a++)
#pragma unroll
                for (int b = 0; b < 4; b++)
                    acc[a][b] = fmaf(ra[a], rb[b], acc[a][b]);
        }
    }

    float* Pp = P + (size_t)pslice * M * N;
#pragma unroll
    for (int a = 0; a < 8; a++) {
        int m = bm + ty * 8 + a;
        float4 v;
        v.x = acc[a][0]; v.y = acc[a][1]; v.z = acc[a][2]; v.w = acc[a][3];
        *(float4*)(Pp + (size_t)m * N + bn + tx * 4) = v;
    }
}

__global__ __launch_bounds__(256)
void sgemm_splitk(const float* __restrict__ A, const float* __restrict__ B,
                  float* __restrict__ P, int M, int N, int K, int KSL)
{
    splitk_body(A, B, P, M, N, K, KSL, blockIdx.z, blockIdx.z, blockIdx.z);
}

// dual-B: z < NS uses B0, else B1 (same A; P slice z)
__global__ __launch_bounds__(256)
void sgemm_splitk_dualB(const float* __restrict__ A,
                        const float* __restrict__ B0,
                        const float* __restrict__ B1,
                        float* __restrict__ P, int M, int N, int K, int KSL,
                        int NS)
{
    const int z = blockIdx.z;
    const float* B = (z < NS) ? B0 : B1;
    const int s = (z < NS) ? z : z - NS;
    splitk_body(A, B, P, M, N, K, KSL, s, s, z);
}

// dual-A: slices z<NS read A0 (K=KA each), else A1; B row index uses global z.
// Implements C = [A0 | A1] @ B without materializing the concat.
__global__ __launch_bounds__(256)
void sgemm_splitk_dualA(const float* __restrict__ A0,
                        const float* __restrict__ A1,
                        const float* __restrict__ B,
                        float* __restrict__ P, int M, int N, int KA, int KSL,
                        int NS)
{
    const int z = blockIdx.z;
    const float* A = (z < NS) ? A0 : A1;
    const int as = (z < NS) ? z : z - NS;
    splitk_body(A, B, P, M, N, KA, KSL, as, z, z);
}

__global__ __launch_bounds__(256)
void skreduce(const float* __restrict__ P, int nsl,
              const float* __restrict__ bias, int relu,
              float* __restrict__ C, int MN, int N)
{
    int idx = blockIdx.x * blockDim.x + threadIdx.x;
    if (idx >= MN) return;
    float s = 0.f;
    for (int sl = 0; sl < nsl; sl++) s += P[(size_t)sl * MN + idx];
    if (bias) s += bias[idx % N];
    if (relu) s = fmaxf(s, 0.f);
    C[idx] = s;
}

// dual reduce: first MN -> C0 (slices 0..nsl), second MN -> C1 (slices nsl..2nsl)
__global__ __launch_bounds__(256)
void skreduce_dual(const float* __restrict__ P, int nsl,
                   float* __restrict__ C0, float* __restrict__ C1, int MN)
{
    int idx = blockIdx.x * blockDim.x + threadIdx.x;
    int which = idx >= MN;
    int base = which ? nsl : 0;
    int off = which ? idx - MN : idx;
    float s = 0.f;
    for (int sl = 0; sl < nsl; sl++)
        s += P[(size_t)(base + sl) * MN + off];
    if (which) C1[off] = s; else C0[off] = s;
}

// ---------------------------------------------------------------------------
// Weight transpose + fp16 convert:  W[Kd, Nd] -> Wh [Nd, Kd]
// ---------------------------------------------------------------------------
__global__ void wsplit_kernel(const float* __restrict__ W,
                              unsigned short* __restrict__ Wh,
                              int Kd, int Nd)
{
    __shared__ float tile[32][33];
    const int n0 = blockIdx.x * 32, k0 = blockIdx.y * 32;
    const int tx = threadIdx.x, ty = threadIdx.y;   // 32 x 8
#pragma unroll
    for (int i = 0; i < 32; i += 8)
        tile[ty + i][tx] = W[(size_t)(k0 + ty + i) * Nd + n0 + tx];
    __syncthreads();
#pragma unroll
    for (int i = 0; i < 32; i += 8) {
        Wh[(size_t)(n0 + ty + i) * Kd + k0 + tx] = f2h_bits(tile[tx][ty + i]);
    }
}

// ---------------------------------------------------------------------------
// Geo embedding + 3-layer 64-wide MLP (fused) -> fp16 output
// ---------------------------------------------------------------------------
__global__ __launch_bounds__(128)
void geo_kernel(const float* __restrict__ prop,
                const float* __restrict__ w1, const float* __restrict__ b1,
                const float* __restrict__ w2, const float* __restrict__ b2,
                const float* __restrict__ w3, const float* __restrict__ b3,
                unsigned short* __restrict__ G3)
{
    __shared__ float sw1[GEO * GEO], sw2[GEO * GEO], sw3[GEO * GEO];
    __shared__ float sb1[GEO], sb2[GEO], sb3[GEO];
    __shared__ float esm[128 * 65];

    const int tid = threadIdx.x;
    for (int t = tid; t < GEO * GEO; t += blockDim.x) {
        sw1[t] = w1[t]; sw2[t] = w2[t]; sw3[t] = w3[t];
    }
    for (int t = tid; t < GEO; t += blockDim.x) {
        sb1[t] = b1[t]; sb2[t] = b2[t]; sb3[t] = b3[t];
    }
    __syncthreads();

    const int row = blockIdx.x * blockDim.x + tid;
    const int b = row >> 14;
    const int i = (row >> 7) & (NP - 1);
    const int j = row & (NP - 1);

    const float* pi = prop + ((size_t)(b * NP + i)) * 4;
    const float* pj = prop + ((size_t)(b * NP + j)) * 4;
    float wi = pi[2] - pi[0] + 1.f, hi = pi[3] - pi[1] + 1.f;
    float wj = pj[2] - pj[0] + 1.f, hj = pj[3] - pj[1] + 1.f;
    float cxi = 0.5f * (pi[0] + pi[2]), cyi = 0.5f * (pi[1] + pi[3]);
    float cxj = 0.5f * (pj[0] + pj[2]), cyj = 0.5f * (pj[1] + pj[3]);

    float pos[4];
    pos[0] = (cxi - cxj) / wj;
    pos[1] = (cyi - cyj) / hj;
    pos[2] = wi / wj;
    pos[3] = hi / hj;

    const float dm[8] = {1.0f, 2.3713737f, 5.6234133f, 13.335215f,
                         31.622777f, 74.989421f, 177.82794f, 421.69650f};

    float* my = &esm[tid * 65];
#pragma unroll
    for (int p = 0; p < 4; p++) {
        float lp = logf(fmaxf(fabsf(pos[p]), 1e-3f)) * 100.f;
#pragma unroll
        for (int r = 0; r < 8; r++) {
            float arg = lp / dm[r];
            float s, c;
            sincosf(arg, &s, &c);
            my[p * 16 + r] = s;
            my[p * 16 + 8 + r] = c;
        }
    }

    float acc[GEO];
#pragma unroll
    for (int o = 0; o < GEO; o++) acc[o] = sb1[o];
    for (int k = 0; k < GEO; k++) {
        float ek = my[k];
        const float* wr = &sw1[k * GEO];
#pragma unroll
        for (int o = 0; o < GEO; o++) acc[o] = fmaf(ek, wr[o], acc[o]);
    }
#pragma unroll
    for (int o = 0; o < GEO; o++) my[o] = fmaxf(acc[o], 0.f);

#pragma unroll
    for (int o = 0; o < GEO; o++) acc[o] = sb2[o];
    for (int k = 0; k < GEO; k++) {
        float ek = my[k];
        const float* wr = &sw2[k * GEO];
#pragma unroll
        for (int o = 0; o < GEO; o++) acc[o] = fmaf(ek, wr[o], acc[o]);
    }
#pragma unroll
    for (int o = 0; o < GEO; o++) my[o] = fmaxf(acc[o], 0.f);

#pragma unroll
    for (int o = 0; o < GEO; o++) acc[o] = sb3[o];
    for (int k = 0; k < GEO; k++) {
        float ek = my[k];
        const float* wr = &sw3[k * GEO];
#pragma unroll
        for (int o = 0; o < GEO; o++) acc[o] = fmaf(ek, wr[o], acc[o]);
    }
    unsigned short* outp = G3 + (size_t)row * GEO;
#pragma unroll
    for (int o = 0; o < GEO; o++) outp[o] = f2h_bits(acc[o]);
}

// ---------------------------------------------------------------------------
// heads
// ---------------------------------------------------------------------------
__global__ __launch_bounds__(128)
void heads_kernel(const float* __restrict__ X,
                  const float* __restrict__ subject,
                  const float* __restrict__ obj,
                  const float* __restrict__ cs_w, const float* __restrict__ cs_b,
                  const float* __restrict__ cso_w, const float* __restrict__ cso_b,
                  float* __restrict__ out)
{
    int row = blockIdx.x;
    int b = row >> 7;
    int tid = threadIdx.x;

    float as = 0.f, ao = 0.f;
    for (int k = tid; k < DIM; k += 128) {
        float xv = X[(size_t)row * DIM + k];
        float sv = subject[(size_t)b * DIM + k];
        float ov = obj[(size_t)b * DIM + k];
        as += xv * cs_w[k] + sv * cs_w[DIM + k];
        ao += xv * cso_w[k] + ov * cso_w[DIM + k];
    }
    __shared__ float rs[128], ro[128];
    rs[tid] = as; ro[tid] = ao;
    __syncthreads();
    for (int s = 64; s > 0; s >>= 1) {
        if (tid < s) { rs[tid] += rs[tid + s]; ro[tid] += ro[tid + s]; }
        __syncthreads();
    }
    if (tid == 0) {
        float s1 = rs[0] + cs_b[0];
        float s2 = ro[0] + cso_b[0];
        out[row * 2 + 0] = 1.f / (1.f + expf(-s1));
        out[row * 2 + 1] = 1.f / (1.f + expf(-s2));
    }
}

// ---------------------------------------------------------------------------
// Launch (graph-forked prologue: geo/W2/W3 on a side stream ∥ FA/FB on main)
// ---------------------------------------------------------------------------
extern "C" void kernel_launch(void* const* d_in, const int* in_sizes, int n_in,
                              void* d_out, int out_size)
{
    const float* feats   = (const float*)d_in[0];
    const float* subject = (const float*)d_in[1];
    const float* obj     = (const float*)d_in[2];
    const float* prop    = (const float*)d_in[3];
    const float* gp_w1 = (const float*)d_in[4];
    const float* gp_b1 = (const float*)d_in[5];
    const float* gp_w2 = (const float*)d_in[6];
    const float* gp_b2 = (const float*)d_in[7];
    const float* gp_w3 = (const float*)d_in[8];
    const float* gp_b3 = (const float*)d_in[9];
    const float* pm_w1 = (const float*)d_in[10];
    const float* pm_b1 = (const float*)d_in[11];
    const float* pm_w2 = (const float*)d_in[12];
    const float* pm_b2 = (const float*)d_in[13];
    const float* pm_w3 = (const float*)d_in[14];
    const float* pm_b3 = (const float*)d_in[15];
    const float* ag_w1 = (const float*)d_in[16];
    const float* ag_b1 = (const float*)d_in[17];
    const float* ag_w2 = (const float*)d_in[18];
    const float* ag_b2 = (const float*)d_in[19];
    const float* ag_w3 = (const float*)d_in[20];
    const float* ag_b3 = (const float*)d_in[21];
    const float* cs_w  = (const float*)d_in[22];
    const float* cs_b  = (const float*)d_in[23];
    const float* cso_w = (const float*)d_in[24];
    const float* cso_b = (const float*)d_in[25];
    float* out = (float*)d_out;

    float *FA, *FB, *T, *SA, *SB, *P;
    unsigned short *G3, *H1, *H2, *W1, *W2, *W3;
    cudaGetSymbolAddress((void**)&FA, g_FA);
    cudaGetSymbolAddress((void**)&FB, g_FB);
    cudaGetSymbolAddress((void**)&T,  g_T);
    cudaGetSymbolAddress((void**)&SA, g_SA);
    cudaGetSymbolAddress((void**)&SB, g_SB);
    cudaGetSymbolAddress((void**)&P,  g_P);
    cudaGetSymbolAddress((void**)&G3, g_G3);
    cudaGetSymbolAddress((void**)&H1, g_H1);
    cudaGetSymbolAddress((void**)&H2, g_H2);
    cudaGetSymbolAddress((void**)&W1, g_W1);
    cudaGetSymbolAddress((void**)&W2, g_W2);
    cudaGetSymbolAddress((void**)&W3, g_W3);

    cudaFuncSetAttribute(hmma_l2_kernel,
                         cudaFuncAttributeMaxDynamicSharedMemorySize, HMMA_SMEM);
    cudaFuncSetAttribute(hmma_l3_topk_kernel,
                         cudaFuncAttributeMaxDynamicSharedMemorySize, HMMA_SMEM);
    cudaFuncSetAttribute(hmma_l1_kernel,
                         cudaFuncAttributeMaxDynamicSharedMemorySize, L1_SMEM);

    dim3 ghm(DIM / 128, MBIG / 128);          // (8, 256)
    dim3 gws(DIM / 32, DIM / 32);
    dim3 gws1(DIM / 32, GEO / 32);
    const int MN = MSMALL * DIM;              // 262144

    // ---- forked prologue ----
    cudaStream_t s1;
    cudaEvent_t eFork, eJoin;
    bool forked =
        (cudaStreamCreateWithFlags(&s1, cudaStreamNonBlocking) == cudaSuccess) &&
        (cudaEventCreateWithFlags(&eFork, cudaEventDisableTiming) == cudaSuccess) &&
        (cudaEventCreateWithFlags(&eJoin, cudaEventDisableTiming) == cudaSuccess);

    if (forked) forked = (cudaEventRecord(eFork, 0) == cudaSuccess) &&
                         (cudaStreamWaitEvent(s1, eFork, 0) == cudaSuccess);

    cudaStream_t sb = forked ? s1 : 0;

    // branch B: W2/W3 convert + geo (feeds l2/l3 and l1's A operand)
    wsplit_kernel<<<gws, dim3(32, 8), 0, sb>>>(pm_w2, W2, DIM, DIM);
    wsplit_kernel<<<gws, dim3(32, 8), 0, sb>>>(pm_w3, W3, DIM, DIM);
    geo_kernel<<<MBIG / 128, 128, 0, sb>>>(prop, gp_w1, gp_b1, gp_w2, gp_b2,
                                           gp_w3, gp_b3, G3);

    // main branch: W1 convert + FA/FB split-K
    wsplit_kernel<<<gws1, dim3(32, 8)>>>(pm_w1 + (size_t)2 * DIM * DIM,
                                         W1, GEO, DIM);
    dim3 gskd(DIM / SKN, MSMALL / SKM, 32);   // 1024 CTAs
    sgemm_splitk_dualB<<<gskd, 256>>>(feats, pm_w1, pm_w1 + (size_t)DIM * DIM,
                                      P, MSMALL, DIM, DIM, 64, 16);
    skreduce_dual<<<(2 * MN) / 256, 256>>>(P, 16, FA, FB, MN);

    if (forked) {
        cudaEventRecord(eJoin, s1);
        cudaStreamWaitEvent(0, eJoin, 0);
    }

    // Pairwise layer 1 (fp16 HMMA, K=64) -> H1 fp16
    hmma_l1_kernel<<<ghm, 256, L1_SMEM>>>(G3, W1, pm_b1, FA, FB, H1);

    // Pairwise layer 2 (fp16 HMMA) -> H2 fp16, relu
    hmma_l2_kernel<<<ghm, 256, HMMA_SMEM>>>(H1, W2, pm_b2, H2);
    // Pairwise layer 3 + fused top-18 sum -> T directly
    hmma_l3_topk_kernel<<<ghm, 256, HMMA_SMEM>>>(H2, W3, pm_b3, T);

    // Aggregate MLP via split-K; ag1 reads [feats | T] via dual-A (no concat)
    dim3 gsk(DIM / SKN, MSMALL / SKM, 16);
    dim3 gsk32(DIM / SKN, MSMALL / SKM, 32);  // K=2048, 32 slices
    sgemm_splitk_dualA<<<gsk32, 256>>>(feats, T, ag_w1, P,
                                       MSMALL, DIM, DIM, 64, 16);
    skreduce<<<MN / 256, 256>>>(P, 32, ag_b1, 1, SA, MN, DIM);
    sgemm_splitk<<<gsk, 256>>>(SA, ag_w2, P, MSMALL, DIM, DIM, 64);
    skreduce<<<MN / 256, 256>>>(P, 16, ag_b2, 1, SB, MN, DIM);
    sgemm_splitk<<<gsk, 256>>>(SB, ag_w3, P, MSMALL, DIM, DIM, 64);
    skreduce<<<MN / 256, 256>>>(P, 16, ag_b3, 0, SA, MN, DIM);

    // Heads
    heads_kernel<<<MSMALL, 128>>>(SA, subject, obj, cs_w, cs_b, cso_w, cso_b, out);
}

// round 13
// speedup vs baseline: 1.0512x; 1.0155x over previous
#include <cuda_runtime.h>
#include <cuda_fp16.h>
#include <cstdint>
#include <cstddef>

// ---------------------------------------------------------------------------
// Problem constants
// ---------------------------------------------------------------------------
#define BSZ 2
#define NP  128
#define DIM 1024
#define GEO 64
#define TOPK 18
#define MBIG (BSZ * NP * NP)     // 32768 pairwise rows
#define MSMALL (BSZ * NP)        // 256 proposal rows

// ---------------------------------------------------------------------------
// Scratch (static device globals)
// ---------------------------------------------------------------------------
__device__ float g_FA[MSMALL * DIM];
__device__ float g_FB[MSMALL * DIM];
__device__ float g_T[MSMALL * DIM];
__device__ float g_SA[MSMALL * DIM];
__device__ float g_SB[MSMALL * DIM];
__device__ float g_P[32 * MSMALL * DIM];         // split-K partials (32 MB)
__device__ unsigned short g_G3[MBIG * GEO];      // geo out fp16 (4 MB)
__device__ unsigned short g_H1[(size_t)MBIG * DIM];  // fp16, 64 MB
__device__ unsigned short g_H2[(size_t)MBIG * DIM];  // fp16, 64 MB
__device__ unsigned short g_W1[DIM * GEO];       // [N,K] w1 geo slice fp16
__device__ unsigned short g_W2[DIM * DIM];       // [N,K] fp16
__device__ unsigned short g_W3[DIM * DIM];       // [N,K] fp16

// ---------------------------------------------------------------------------
// Helpers (sm_80+ only: cp.async, ldmatrix, mma.sync)
// ---------------------------------------------------------------------------
__device__ __forceinline__ uint32_t smem_u32(const void* p) {
    uint32_t a;
    asm("{ .reg .u64 t; cvta.to.shared.u64 t, %1; cvt.u32.u64 %0, t; }"
        : "=r"(a) : "l"(p));
    return a;
}
__device__ __forceinline__ void cp16(uint32_t dst, const void* src) {
    asm volatile("cp.async.cg.shared.global [%0], [%1], 16;" :: "r"(dst), "l"(src));
}
__device__ __forceinline__ void cp_commit() {
    asm volatile("cp.async.commit_group;" ::: "memory");
}
template<int N> __device__ __forceinline__ void cp_wait() {
    asm volatile("cp.async.wait_group %0;" :: "n"(N) : "memory");
}
#define SWZ128(o) ((o) ^ (((o) >> 3) & 0x70))

__device__ __forceinline__ void ldsm4(uint32_t& r0, uint32_t& r1,
                                      uint32_t& r2, uint32_t& r3, uint32_t addr) {
    asm volatile("ldmatrix.sync.aligned.m8n8.x4.shared.b16 {%0,%1,%2,%3}, [%4];"
                 : "=r"(r0), "=r"(r1), "=r"(r2), "=r"(r3) : "r"(addr));
}
__device__ __forceinline__ void mma_f16(float* c,
                                        const uint32_t* a, const uint32_t* b) {
    asm volatile("mma.sync.aligned.m16n8k16.row.col.f32.f16.f16.f32 "
                 "{%0,%1,%2,%3}, {%4,%5,%6,%7}, {%8,%9}, {%0,%1,%2,%3};"
                 : "+f"(c[0]), "+f"(c[1]), "+f"(c[2]), "+f"(c[3])
                 : "r"(a[0]), "r"(a[1]), "r"(a[2]), "r"(a[3]),
                   "r"(b[0]), "r"(b[1]));
}

__device__ __forceinline__ unsigned short f2h_bits(float v) {
    __half h = __float2half_rn(v);
    return *reinterpret_cast<unsigned short*>(&h);
}

// ---------------------------------------------------------------------------
// fp16 HMMA mainloop (128x128 CTA tile; 8 warps 2(M)x4(N); warp tile 64x32).
// K chunk 64 (128B rows, SW128). 3-stage cp.async pipeline, 32 KB/stage,
// 2 CTAs/SM, 256 threads/CTA. SINGLE __syncthreads per k-chunk: loads are
// issued after the barrier, so the stage written (== stage computed last
// iteration) is provably quiescent.
// ---------------------------------------------------------------------------
#define KCH 64
#define NKC (DIM / KCH)            // 16
#define STG_BYTES 32768
#define HMMA_SMEM (3 * STG_BYTES + 128)

struct HmmaCtx {
    uint32_t sbase;
    int tid, lane, wm, wn, mtile, ntile;
};

__device__ __forceinline__ void hmma_mainloop(
    const HmmaCtx& c,
    const unsigned short* __restrict__ A,
    const unsigned short* __restrict__ B,
    float acc[4][4][4])
{
#pragma unroll
    for (int mf = 0; mf < 4; mf++)
#pragma unroll
        for (int nf = 0; nf < 4; nf++)
#pragma unroll
            for (int e = 0; e < 4; e++) acc[mf][nf][e] = 0.f;

    auto load_chunk = [&](int kc, int stg) {
        const uint32_t s0 = c.sbase + (uint32_t)stg * STG_BYTES;
#pragma unroll
        for (int it = 0; it < 4; it++) {
            int t = c.tid + (it << 8);
            int rr = t >> 3, ss = t & 7;
            cp16(s0 + SWZ128((uint32_t)(rr * 128 + ss * 16)),
                 A + (size_t)((c.mtile << 7) + rr) * DIM + kc * KCH + ss * 8);
        }
#pragma unroll
        for (int it = 0; it < 4; it++) {
            int t = c.tid + (it << 8);
            int rr = t >> 3, ss = t & 7;
            cp16(s0 + 16384u + SWZ128((uint32_t)(rr * 128 + ss * 16)),
                 B + (size_t)((c.ntile << 7) + rr) * DIM + kc * KCH + ss * 8);
        }
        cp_commit();
    };

    const int a_rl = c.lane & 15;
    const int a_cl = (c.lane >> 4) << 3;
    const int b_rl = (c.lane & 7) + ((c.lane >> 4) << 3);
    const int b_cl = ((c.lane >> 3) & 1) << 3;

    auto compute = [&](int stg) {
        const uint32_t s0 = c.sbase + (uint32_t)stg * STG_BYTES;
        const uint32_t sA = s0, sB = s0 + 16384u;
#pragma unroll
        for (int ks = 0; ks < 4; ks++) {
            const int k0 = ks * 16;
            uint32_t bf[4][2];
#pragma unroll
            for (int np = 0; np < 2; np++) {
                const int n0 = c.wn * 32 + np * 16;
                const uint32_t off =
                    SWZ128((uint32_t)((n0 + b_rl) * 128 + (k0 + b_cl) * 2));
                uint32_t r0, r1, r2, r3;
                ldsm4(r0, r1, r2, r3, sB + off);
                bf[np * 2][0] = r0; bf[np * 2][1] = r1;
                bf[np * 2 + 1][0] = r2; bf[np * 2 + 1][1] = r3;
            }
            uint32_t af[4][4];
#pragma unroll
            for (int mf = 0; mf < 4; mf++) {
                const int m0 = c.wm * 64 + mf * 16;
                const uint32_t off =
                    SWZ128((uint32_t)((m0 + a_rl) * 128 + (k0 + a_cl) * 2));
                ldsm4(af[mf][0], af[mf][1], af[mf][2], af[mf][3], sA + off);
            }
#pragma unroll
            for (int mf = 0; mf < 4; mf++)
#pragma unroll
                for (int nf = 0; nf < 4; nf++)
                    mma_f16(acc[mf][nf], af[mf], bf[nf]);
        }
    };

    load_chunk(0, 0);
    load_chunk(1, 1);
    for (int kc = 0; kc < NKC; kc++) {
        if (kc + 1 < NKC) {
            cp_wait<1>();          // stage kc complete (1 younger group allowed)
        } else {
            cp_wait<0>();
        }
        __syncthreads();           // all warps done with stage (kc-1)%3
        if (kc + 2 < NKC) load_chunk(kc + 2, (kc + 2) % 3);  // writes (kc-1)%3
        compute(kc % 3);
    }
}

// Layer 2: out = relu(A @ B^T + bias) -> fp16
__global__ void __launch_bounds__(256, 2)
hmma_l2_kernel(const unsigned short* __restrict__ A,
               const unsigned short* __restrict__ B,
               const float* __restrict__ bias,
               unsigned short* __restrict__ outH)
{
    extern __shared__ char smem_raw[];
    HmmaCtx c;
    c.sbase = (smem_u32(smem_raw) + 127u) & ~127u;
    c.tid = threadIdx.x;
    c.lane = c.tid & 31;
    const int w = c.tid >> 5;
    c.wm = w >> 2; c.wn = w & 3;
    c.mtile = blockIdx.y; c.ntile = blockIdx.x;

    float acc[4][4][4];
    hmma_mainloop(c, A, B, acc);

    const int rl = c.lane >> 2;
    const int cl = (c.lane & 3) << 1;
#pragma unroll
    for (int mf = 0; mf < 4; mf++) {
        const int m_base = (c.mtile << 7) + c.wm * 64 + mf * 16 + rl;
#pragma unroll
        for (int nf = 0; nf < 4; nf++) {
            const int n = (c.ntile << 7) + c.wn * 32 + nf * 8 + cl;
            const float b0 = bias[n], b1 = bias[n + 1];
#pragma unroll
            for (int half = 0; half < 2; half++) {
                const int m = m_base + half * 8;
                float v0 = fmaxf(acc[mf][nf][half * 2 + 0] + b0, 0.f);
                float v1 = fmaxf(acc[mf][nf][half * 2 + 1] + b1, 0.f);
                *(uint32_t*)(outH + (size_t)m * DIM + n) =
                    (uint32_t)f2h_bits(v0) | ((uint32_t)f2h_bits(v1) << 16);
            }
        }
    }
}

// Layer 3 fused with top-18-sum. CTA M-tile (128 rows) = full j-range of one
// (b,i): topk is CTA-local. Stage fp32 tile in reused pipeline smem, 256
// threads scan 64 rows each (2 per column), merge pairs, write T directly.
#define TPAD 132
#define L3_LISTS (128 * TPAD * 4)   // byte offset of merge lists in smem

__global__ void __launch_bounds__(256, 2)
hmma_l3_topk_kernel(const unsigned short* __restrict__ A,
                    const unsigned short* __restrict__ B,
                    const float* __restrict__ bias,
                    float* __restrict__ T)
{
    extern __shared__ char smem_raw[];
    HmmaCtx c;
    c.sbase = (smem_u32(smem_raw) + 127u) & ~127u;
    c.tid = threadIdx.x;
    c.lane = c.tid & 31;
    const int w = c.tid >> 5;
    c.wm = w >> 2; c.wn = w & 3;
    c.mtile = blockIdx.y; c.ntile = blockIdx.x;

    float acc[4][4][4];
    hmma_mainloop(c, A, B, acc);
    __syncthreads();   // all warps done reading pipeline smem before reuse

    // stage fp32 tile [128 rows(j)][128 cols] in smem (reuse pipeline space)
    char* sm_c = smem_raw + (c.sbase - smem_u32(smem_raw));
    float* smf = (float*)sm_c;
    const int rl = c.lane >> 2;
    const int cl = (c.lane & 3) << 1;
#pragma unroll
    for (int mf = 0; mf < 4; mf++) {
        const int ml_base = c.wm * 64 + mf * 16 + rl;
#pragma unroll
        for (int nf = 0; nf < 4; nf++) {
            const int nl = c.wn * 32 + nf * 8 + cl;
            const int n = (c.ntile << 7) + nl;
            const float b0 = bias[n], b1 = bias[n + 1];
#pragma unroll
            for (int half = 0; half < 2; half++) {
                const int ml = ml_base + half * 8;
                smf[ml * TPAD + nl] = acc[mf][nf][half * 2 + 0] + b0;
                smf[ml * TPAD + nl + 1] = acc[mf][nf][half * 2 + 1] + b1;
            }
        }
    }
    __syncthreads();

    // two threads per column: thread t handles column t&127, rows half*64..+64
    const int cidx = c.tid & 127;
    const int half = c.tid >> 7;
    float t18[TOPK];
#pragma unroll
    for (int s = 0; s < TOPK; s++) t18[s] = -3.4e38f;
    const float* colp = smf + half * 64 * TPAD + cidx;
    for (int j = 0; j < 64; j++) {
        float v = colp[j * TPAD];
        if (v > t18[TOPK - 1]) {
            t18[TOPK - 1] = v;
#pragma unroll
            for (int s = TOPK - 1; s > 0; s--) {
                if (t18[s] > t18[s - 1]) {
                    float tmp = t18[s - 1]; t18[s - 1] = t18[s]; t18[s] = tmp;
                }
            }
        }
    }
    float* lists = (float*)(sm_c + L3_LISTS);
    if (half == 1) {
#pragma unroll
        for (int s = 0; s < TOPK; s++) lists[cidx * TOPK + s] = t18[s];
    }
    __syncthreads();
    if (half == 0) {
#pragma unroll
        for (int s = 0; s < TOPK; s++) {
            float v = lists[cidx * TOPK + s];
            if (v > t18[TOPK - 1]) {
                t18[TOPK - 1] = v;
#pragma unroll
                for (int q = TOPK - 1; q > 0; q--) {
                    if (t18[q] > t18[q - 1]) {
                        float tmp = t18[q - 1]; t18[q - 1] = t18[q]; t18[q] = tmp;
                    }
                }
            }
        }
        float sum = 0.f;
#pragma unroll
        for (int s = 0; s < TOPK; s++) sum += t18[s];
        T[(size_t)c.mtile * DIM + (c.ntile << 7) + cidx] = sum * 0.125f;
    }
}

// ---------------------------------------------------------------------------
// Layer-1 fp16 HMMA (K=64): H1 = relu( G3 @ W1g^T + FA_j + FB_i + b1 )
// ---------------------------------------------------------------------------
#define L1_SMEM (2 * 16384 + 128)

__global__ void __launch_bounds__(256, 3)
hmma_l1_kernel(const unsigned short* __restrict__ A,   // G3 fp16 [MBIG, 64]
               const unsigned short* __restrict__ B,   // W1g fp16 [1024, 64]
               const float* __restrict__ bias,
               const float* __restrict__ FA,
               const float* __restrict__ FB,
               unsigned short* __restrict__ outH)
{
    extern __shared__ char smem_raw[];
    const uint32_t sbase = (smem_u32(smem_raw) + 127u) & ~127u;
    const int tid = threadIdx.x;
    const int mtile = blockIdx.y, ntile = blockIdx.x;
    const int lane = tid & 31;
    const int w = tid >> 5;
    const int wm = w >> 2;
    const int wn = w & 3;

#pragma unroll
    for (int it = 0; it < 4; it++) {
        int t = tid + (it << 8);
        int rr = t >> 3, ss = t & 7;
        cp16(sbase + SWZ128((uint32_t)(rr * 128 + ss * 16)),
             A + (size_t)((mtile << 7) + rr) * GEO + ss * 8);
    }
#pragma unroll
    for (int it = 0; it < 4; it++) {
        int t = tid + (it << 8);
        int rr = t >> 3, ss = t & 7;
        cp16(sbase + 16384u + SWZ128((uint32_t)(rr * 128 + ss * 16)),
             B + (size_t)((ntile << 7) + rr) * GEO + ss * 8);
    }
    cp_commit();

    float acc[4][4][4];
#pragma unroll
    for (int mf = 0; mf < 4; mf++)
#pragma unroll
        for (int nf = 0; nf < 4; nf++)
#pragma unroll
            for (int e = 0; e < 4; e++) acc[mf][nf][e] = 0.f;

    const int a_rl = lane & 15;
    const int a_cl = (lane >> 4) << 3;
    const int b_rl = (lane & 7) + ((lane >> 4) << 3);
    const int b_cl = ((lane >> 3) & 1) << 3;

    cp_wait<0>();
    __syncthreads();

    const uint32_t sA = sbase, sB = sbase + 16384u;
#pragma unroll
    for (int ks = 0; ks < 4; ks++) {
        const int k0 = ks * 16;
        uint32_t bf[4][2];
#pragma unroll
        for (int np = 0; np < 2; np++) {
            const int n0 = wn * 32 + np * 16;
            const uint32_t off =
                SWZ128((uint32_t)((n0 + b_rl) * 128 + (k0 + b_cl) * 2));
            uint32_t r0, r1, r2, r3;
            ldsm4(r0, r1, r2, r3, sB + off);
            bf[np * 2][0] = r0; bf[np * 2][1] = r1;
            bf[np * 2 + 1][0] = r2; bf[np * 2 + 1][1] = r3;
        }
        uint32_t af[4][4];
#pragma unroll
        for (int mf = 0; mf < 4; mf++) {
            const int m0 = wm * 64 + mf * 16;
            const uint32_t off =
                SWZ128((uint32_t)((m0 + a_rl) * 128 + (k0 + a_cl) * 2));
            ldsm4(af[mf][0], af[mf][1], af[mf][2], af[mf][3], sA + off);
        }
#pragma unroll
        for (int mf = 0; mf < 4; mf++)
#pragma unroll
            for (int nf = 0; nf < 4; nf++)
                mma_f16(acc[mf][nf], af[mf], bf[nf]);
    }

    const int rl = lane >> 2;
    const int cl = (lane & 3) << 1;
#pragma unroll
    for (int mf = 0; mf < 4; mf++) {
        const int m_base = (mtile << 7) + wm * 64 + mf * 16 + rl;
#pragma unroll
        for (int nf = 0; nf < 4; nf++) {
            const int n = (ntile << 7) + wn * 32 + nf * 8 + cl;
            const float b0 = bias[n], b1 = bias[n + 1];
#pragma unroll
            for (int half = 0; half < 2; half++) {
                const int m = m_base + half * 8;
                const int j = m & (NP - 1);
                const int bi = m >> 7;
                const int bb = bi >> 7;
                const float* aJ = FA + (size_t)((bb << 7) + j) * DIM;
                const float* aI = FB + (size_t)bi * DIM;
                float v0 = acc[mf][nf][half * 2 + 0] + b0 + aJ[n] + aI[n];
                float v1 = acc[mf][nf][half * 2 + 1] + b1 + aJ[n + 1] + aI[n + 1];
                v0 = fmaxf(v0, 0.f); v1 = fmaxf(v1, 0.f);
                *(uint32_t*)(outH + (size_t)m * DIM + n) =
                    (uint32_t)f2h_bits(v0) | ((uint32_t)f2h_bits(v1) << 16);
            }
        }
    }
}

// ---------------------------------------------------------------------------
// Split-K SGEMM for small-M GEMMs (aslice for A, bslice for B, pslice for P)
// ---------------------------------------------------------------------------
#define SKM 64
#define SKN 128

__device__ __forceinline__ void splitk_body(
    const float* __restrict__ A, const float* __restrict__ B,
    float* __restrict__ P, int M, int N, int K, int KSL,
    int aslice, int bslice, int pslice)
{
    __shared__ float As[16][SKM + 4];
    __shared__ float Bs[16][SKN];

    const int bm = blockIdx.y * SKM;
    const int bn = blockIdx.x * SKN;
    const int tid = threadIdx.x;
    const int arow = tid >> 2, acol = (tid & 3) << 2;
    const int brow = tid >> 5, bcol = (tid & 31) << 2;
    const int tx = tid & 31;
    const int ty = tid >> 5;

    float acc[8][4];
#pragma unroll
    for (int a = 0; a < 8; a++)
#pragma unroll
        for (int b = 0; b < 4; b++) acc[a][b] = 0.f;

    const float* Aptr = A + (size_t)(bm + arow) * K + aslice * KSL + acol;
    const float* Bptr = B + (size_t)(bslice * KSL + brow) * N + bn + bcol;

    for (int k0 = 0; k0 < KSL; k0 += 16) {
        float4 a0 = *(const float4*)(Aptr + k0);
        float4 b0 = *(const float4*)(Bptr + (size_t)k0 * N);
        float4 b1 = *(const float4*)(Bptr + (size_t)(k0 + 8) * N);
        __syncthreads();
        As[acol + 0][arow] = a0.x; As[acol + 1][arow] = a0.y;
        As[acol + 2][arow] = a0.z; As[acol + 3][arow] = a0.w;
        *(float4*)&Bs[brow][bcol] = b0;
        *(float4*)&Bs[brow + 8][bcol] = b1;
        __syncthreads();
#pragma unroll
        for (int kk = 0; kk < 16; kk++) {
            float ra[8], rb[4];
#pragma unroll
            for (int a = 0; a < 8; a++) ra[a] = As[kk][ty * 8 + a];
#pragma unroll
            for (int b = 0; b < 4; b++) rb[b] = Bs[kk][tx * 4 + b];
#pragma unroll
            for (int a = 0; a < 8; a++)
#pragma unroll
                for (int b = 0; b < 4; b++)
                    acc[a][b] = fmaf(ra[a], rb[b], acc[a][b]);
        }
    }

    float* Pp = P + (size_t)pslice * M * N;
#pragma unroll
    for (int a = 0; a < 8; a++) {
        int m = bm + ty * 8 + a;
        float4 v;
        v.x = acc[a][0]; v.y = acc[a][1]; v.z = acc[a][2]; v.w = acc[a][3];
        *(float4*)(Pp + (size_t)m * N + bn + tx * 4) = v;
    }
}

__global__ __launch_bounds__(256)
void sgemm_splitk(const float* __restrict__ A, const float* __restrict__ B,
                  float* __restrict__ P, int M, int N, int K, int KSL)
{
    splitk_body(A, B, P, M, N, K, KSL, blockIdx.z, blockIdx.z, blockIdx.z);
}

// dual-B: z < NS uses B0, else B1 (same A; P slice z)
__global__ __launch_bounds__(256)
void sgemm_splitk_dualB(const float* __restrict__ A,
                        const float* __restrict__ B0,
                        const float* __restrict__ B1,
                        float* __restrict__ P, int M, int N, int K, int KSL,
                        int NS)
{
    const int z = blockIdx.z;
    const float* B = (z < NS) ? B0 : B1;
    const int s = (z < NS) ? z : z - NS;
    splitk_body(A, B, P, M, N, K, KSL, s, s, z);
}

// dual-A: slices z<NS read A0 (K=KA each), else A1; B row index uses global z.
// Implements C = [A0 | A1] @ B without materializing the concat.
__global__ __launch_bounds__(256)
void sgemm_splitk_dualA(const float* __restrict__ A0,
                        const float* __restrict__ A1,
                        const float* __restrict__ B,
                        float* __restrict__ P, int M, int N, int KA, int KSL,
                        int NS)
{
    const int z = blockIdx.z;
    const float* A = (z < NS) ? A0 : A1;
    const int as = (z < NS) ? z : z - NS;
    splitk_body(A, B, P, M, N, KA, KSL, as, z, z);
}

__global__ __launch_bounds__(256)
void skreduce(const float* __restrict__ P, int nsl,
              const float* __restrict__ bias, int relu,
              float* __restrict__ C, int MN, int N)
{
    int idx = blockIdx.x * blockDim.x + threadIdx.x;
    if (idx >= MN) return;
    float s = 0.f;
    for (int sl = 0; sl < nsl; sl++) s += P[(size_t)sl * MN + idx];
    if (bias) s += bias[idx % N];
    if (relu) s = fmaxf(s, 0.f);
    C[idx] = s;
}

// dual reduce: first MN -> C0 (slices 0..nsl), second MN -> C1 (slices nsl..2nsl)
__global__ __launch_bounds__(256)
void skreduce_dual(const float* __restrict__ P, int nsl,
                   float* __restrict__ C0, float* __restrict__ C1, int MN)
{
    int idx = blockIdx.x * blockDim.x + threadIdx.x;
    int which = idx >= MN;
    int base = which ? nsl : 0;
    int off = which ? idx - MN : idx;
    float s = 0.f;
    for (int sl = 0; sl < nsl; sl++)
        s += P[(size_t)(base + sl) * MN + off];
    if (which) C1[off] = s; else C0[off] = s;
}

// ---------------------------------------------------------------------------
// Weight transpose + fp16 convert:  W[Kd, Nd] -> Wh [Nd, Kd]
// ---------------------------------------------------------------------------
__global__ void wsplit_kernel(const float* __restrict__ W,
                              unsigned short* __restrict__ Wh,
                              int Kd, int Nd)
{
    __shared__ float tile[32][33];
    const int n0 = blockIdx.x * 32, k0 = blockIdx.y * 32;
    const int tx = threadIdx.x, ty = threadIdx.y;   // 32 x 8
#pragma unroll
    for (int i = 0; i < 32; i += 8)
        tile[ty + i][tx] = W[(size_t)(k0 + ty + i) * Nd + n0 + tx];
    __syncthreads();
#pragma unroll
    for (int i = 0; i < 32; i += 8) {
        Wh[(size_t)(n0 + ty + i) * Kd + k0 + tx] = f2h_bits(tile[tx][ty + i]);
    }
}

// ---------------------------------------------------------------------------
// Geo embedding + 3-layer 64-wide MLP (fused) -> fp16 output
// ---------------------------------------------------------------------------
__global__ __launch_bounds__(128)
void geo_kernel(const float* __restrict__ prop,
                const float* __restrict__ w1, const float* __restrict__ b1,
                const float* __restrict__ w2, const float* __restrict__ b2,
                const float* __restrict__ w3, const float* __restrict__ b3,
                unsigned short* __restrict__ G3)
{
    __shared__ float sw1[GEO * GEO], sw2[GEO * GEO], sw3[GEO * GEO];
    __shared__ float sb1[GEO], sb2[GEO], sb3[GEO];
    __shared__ float esm[128 * 65];

    const int tid = threadIdx.x;
    for (int t = tid; t < GEO * GEO; t += blockDim.x) {
        sw1[t] = w1[t]; sw2[t] = w2[t]; sw3[t] = w3[t];
    }
    for (int t = tid; t < GEO; t += blockDim.x) {
        sb1[t] = b1[t]; sb2[t] = b2[t]; sb3[t] = b3[t];
    }
    __syncthreads();

    const int row = blockIdx.x * blockDim.x + tid;
    const int b = row >> 14;
    const int i = (row >> 7) & (NP - 1);
    const int j = row & (NP - 1);

    const float* pi = prop + ((size_t)(b * NP + i)) * 4;
    const float* pj = prop + ((size_t)(b * NP + j)) * 4;
    float wi = pi[2] - pi[0] + 1.f, hi = pi[3] - pi[1] + 1.f;
    float wj = pj[2] - pj[0] + 1.f, hj = pj[3] - pj[1] + 1.f;
    float cxi = 0.5f * (pi[0] + pi[2]), cyi = 0.5f * (pi[1] + pi[3]);
    float cxj = 0.5f * (pj[0] + pj[2]), cyj = 0.5f * (pj[1] + pj[3]);

    float pos[4];
    pos[0] = (cxi - cxj) / wj;
    pos[1] = (cyi - cyj) / hj;
    pos[2] = wi / wj;
    pos[3] = hi / hj;

    const float dm[8] = {1.0f, 2.3713737f, 5.6234133f, 13.335215f,
                         31.622777f, 74.989421f, 177.82794f, 421.69650f};

    float* my = &esm[tid * 65];
#pragma unroll
    for (int p = 0; p < 4; p++) {
        float lp = logf(fmaxf(fabsf(pos[p]), 1e-3f)) * 100.f;
#pragma unroll
        for (int r = 0; r < 8; r++) {
            float arg = lp / dm[r];
            float s, c;
            sincosf(arg, &s, &c);
            my[p * 16 + r] = s;
            my[p * 16 + 8 + r] = c;
        }
    }

    float acc[GEO];
#pragma unroll
    for (int o = 0; o < GEO; o++) acc[o] = sb1[o];
    for (int k = 0; k < GEO; k++) {
        float ek = my[k];
        const float* wr = &sw1[k * GEO];
#pragma unroll
        for (int o = 0; o < GEO; o++) acc[o] = fmaf(ek, wr[o], acc[o]);
    }
#pragma unroll
    for (int o = 0; o < GEO; o++) my[o] = fmaxf(acc[o], 0.f);

#pragma unroll
    for (int o = 0; o < GEO; o++) acc[o] = sb2[o];
    for (int k = 0; k < GEO; k++) {
        float ek = my[k];
        const float* wr = &sw2[k * GEO];
#pragma unroll
        for (int o = 0; o < GEO; o++) acc[o] = fmaf(ek, wr[o], acc[o]);
    }
#pragma unroll
    for (int o = 0; o < GEO; o++) my[o] = fmaxf(acc[o], 0.f);

#pragma unroll
    for (int o = 0; o < GEO; o++) acc[o] = sb3[o];
    for (int k = 0; k < GEO; k++) {
        float ek = my[k];
        const float* wr = &sw3[k * GEO];
#pragma unroll
        for (int o = 0; o < GEO; o++) acc[o] = fmaf(ek, wr[o], acc[o]);
    }
    unsigned short* outp = G3 + (size_t)row * GEO;
#pragma unroll
    for (int o = 0; o < GEO; o++) outp[o] = f2h_bits(acc[o]);
}

// ---------------------------------------------------------------------------
// heads
// ---------------------------------------------------------------------------
__global__ __launch_bounds__(128)
void heads_kernel(const float* __restrict__ X,
                  const float* __restrict__ subject,
                  const float* __restrict__ obj,
                  const float* __restrict__ cs_w, const float* __restrict__ cs_b,
                  const float* __restrict__ cso_w, const float* __restrict__ cso_b,
                  float* __restrict__ out)
{
    int row = blockIdx.x;
    int b = row >> 7;
    int tid = threadIdx.x;

    float as = 0.f, ao = 0.f;
    for (int k = tid; k < DIM; k += 128) {
        float xv = X[(size_t)row * DIM + k];
        float sv = subject[(size_t)b * DIM + k];
        float ov = obj[(size_t)b * DIM + k];
        as += xv * cs_w[k] + sv * cs_w[DIM + k];
        ao += xv * cso_w[k] + ov * cso_w[DIM + k];
    }
    __shared__ float rs[128], ro[128];
    rs[tid] = as; ro[tid] = ao;
    __syncthreads();
    for (int s = 64; s > 0; s >>= 1) {
        if (tid < s) { rs[tid] += rs[tid + s]; ro[tid] += ro[tid + s]; }
        __syncthreads();
    }
    if (tid == 0) {
        float s1 = rs[0] + cs_b[0];
        float s2 = ro[0] + cso_b[0];
        out[row * 2 + 0] = 1.f / (1.f + expf(-s1));
        out[row * 2 + 1] = 1.f / (1.f + expf(-s2));
    }
}

// ---------------------------------------------------------------------------
// Launch (graph-forked prologue: geo/W2/W3 on a side stream ∥ FA/FB on main)
// ---------------------------------------------------------------------------
extern "C" void kernel_launch(void* const* d_in, const int* in_sizes, int n_in,
                              void* d_out, int out_size)
{
    const float* feats   = (const float*)d_in[0];
    const float* subject = (const float*)d_in[1];
    const float* obj     = (const float*)d_in[2];
    const float* prop    = (const float*)d_in[3];
    const float* gp_w1 = (const float*)d_in[4];
    const float* gp_b1 = (const float*)d_in[5];
    const float* gp_w2 = (const float*)d_in[6];
    const float* gp_b2 = (const float*)d_in[7];
    const float* gp_w3 = (const float*)d_in[8];
    const float* gp_b3 = (const float*)d_in[9];
    const float* pm_w1 = (const float*)d_in[10];
    const float* pm_b1 = (const float*)d_in[11];
    const float* pm_w2 = (const float*)d_in[12];
    const float* pm_b2 = (const float*)d_in[13];
    const float* pm_w3 = (const float*)d_in[14];
    const float* pm_b3 = (const float*)d_in[15];
    const float* ag_w1 = (const float*)d_in[16];
    const float* ag_b1 = (const float*)d_in[17];
    const float* ag_w2 = (const float*)d_in[18];
    const float* ag_b2 = (const float*)d_in[19];
    const float* ag_w3 = (const float*)d_in[20];
    const float* ag_b3 = (const float*)d_in[21];
    const float* cs_w  = (const float*)d_in[22];
    const float* cs_b  = (const float*)d_in[23];
    const float* cso_w = (const float*)d_in[24];
    const float* cso_b = (const float*)d_in[25];
    float* out = (float*)d_out;

    float *FA, *FB, *T, *SA, *SB, *P;
    unsigned short *G3, *H1, *H2, *W1, *W2, *W3;
    cudaGetSymbolAddress((void**)&FA, g_FA);
    cudaGetSymbolAddress((void**)&FB, g_FB);
    cudaGetSymbolAddress((void**)&T,  g_T);
    cudaGetSymbolAddress((void**)&SA, g_SA);
    cudaGetSymbolAddress((void**)&SB, g_SB);
    cudaGetSymbolAddress((void**)&P,  g_P);
    cudaGetSymbolAddress((void**)&G3, g_G3);
    cudaGetSymbolAddress((void**)&H1, g_H1);
    cudaGetSymbolAddress((void**)&H2, g_H2);
    cudaGetSymbolAddress((void**)&W1, g_W1);
    cudaGetSymbolAddress((void**)&W2, g_W2);
    cudaGetSymbolAddress((void**)&W3, g_W3);

    cudaFuncSetAttribute(hmma_l2_kernel,
                         cudaFuncAttributeMaxDynamicSharedMemorySize, HMMA_SMEM);
    cudaFuncSetAttribute(hmma_l3_topk_kernel,
                         cudaFuncAttributeMaxDynamicSharedMemorySize, HMMA_SMEM);
    cudaFuncSetAttribute(hmma_l1_kernel,
                         cudaFuncAttributeMaxDynamicSharedMemorySize, L1_SMEM);

    dim3 ghm(DIM / 128, MBIG / 128);          // (8, 256)
    dim3 gws(DIM / 32, DIM / 32);
    dim3 gws1(DIM / 32, GEO / 32);
    const int MN = MSMALL * DIM;              // 262144

    // ---- forked prologue ----
    cudaStream_t s1;
    cudaEvent_t eFork, eJoin;
    bool forked =
        (cudaStreamCreateWithFlags(&s1, cudaStreamNonBlocking) == cudaSuccess) &&
        (cudaEventCreateWithFlags(&eFork, cudaEventDisableTiming) == cudaSuccess) &&
        (cudaEventCreateWithFlags(&eJoin, cudaEventDisableTiming) == cudaSuccess);

    if (forked) forked = (cudaEventRecord(eFork, 0) == cudaSuccess) &&
                         (cudaStreamWaitEvent(s1, eFork, 0) == cudaSuccess);

    cudaStream_t sb = forked ? s1 : 0;

    // branch B: W2/W3 convert + geo (feeds l2/l3 and l1's A operand)
    wsplit_kernel<<<gws, dim3(32, 8), 0, sb>>>(pm_w2, W2, DIM, DIM);
    wsplit_kernel<<<gws, dim3(32, 8), 0, sb>>>(pm_w3, W3, DIM, DIM);
    geo_kernel<<<MBIG / 128, 128, 0, sb>>>(prop, gp_w1, gp_b1, gp_w2, gp_b2,
                                           gp_w3, gp_b3, G3);

    // main branch: W1 convert + FA/FB split-K
    wsplit_kernel<<<gws1, dim3(32, 8)>>>(pm_w1 + (size_t)2 * DIM * DIM,
                                         W1, GEO, DIM);
    dim3 gskd(DIM / SKN, MSMALL / SKM, 32);   // 1024 CTAs
    sgemm_splitk_dualB<<<gskd, 256>>>(feats, pm_w1, pm_w1 + (size_t)DIM * DIM,
                                      P, MSMALL, DIM, DIM, 64, 16);
    skreduce_dual<<<(2 * MN) / 256, 256>>>(P, 16, FA, FB, MN);

    if (forked) {
        cudaEventRecord(eJoin, s1);
        cudaStreamWaitEvent(0, eJoin, 0);
    }

    // Pairwise layer 1 (fp16 HMMA, K=64) -> H1 fp16
    hmma_l1_kernel<<<ghm, 256, L1_SMEM>>>(G3, W1, pm_b1, FA, FB, H1);

    // Pairwise layer 2 (fp16 HMMA) -> H2 fp16, relu
    hmma_l2_kernel<<<ghm, 256, HMMA_SMEM>>>(H1, W2, pm_b2, H2);
    // Pairwise layer 3 + fused top-18 sum -> T directly
    hmma_l3_topk_kernel<<<ghm, 256, HMMA_SMEM>>>(H2, W3, pm_b3, T);

    // Aggregate MLP via split-K; ag1 reads [feats | T] via dual-A (no concat)
    dim3 gsk(DIM / SKN, MSMALL / SKM, 16);
    dim3 gsk32(DIM / SKN, MSMALL / SKM, 32);  // K=2048, 32 slices
    sgemm_splitk_dualA<<<gsk32, 256>>>(feats, T, ag_w1, P,
                                       MSMALL, DIM, DIM, 64, 16);
    skreduce<<<MN / 256, 256>>>(P, 32, ag_b1, 1, SA, MN, DIM);
    sgemm_splitk<<<gsk, 256>>>(SA, ag_w2, P, MSMALL, DIM, DIM, 64);
    skreduce<<<MN / 256, 256>>>(P, 16, ag_b2, 1, SB, MN, DIM);
    sgemm_splitk<<<gsk, 256>>>(SB, ag_w3, P, MSMALL, DIM, DIM, 64);
    skreduce<<<MN / 256, 256>>>(P, 16, ag_b3, 0, SA, MN, DIM);

    // Heads
    heads_kernel<<<MSMALL, 128>>>(SA, subject, obj, cs_w, cs_b, cso_w, cso_b, out);
}

// round 14
// speedup vs baseline: 1.1558x; 1.0996x over previous
#include <cuda_runtime.h>
#include <cuda_fp16.h>
#include <cstdint>
#include <cstddef>

// ---------------------------------------------------------------------------
// Problem constants
// ---------------------------------------------------------------------------
#define BSZ 2
#define NP  128
#define DIM 1024
#define GEO 64
#define TOPK 18
#define MBIG (BSZ * NP * NP)     // 32768 pairwise rows
#define MSMALL (BSZ * NP)        // 256 proposal rows
#define MN_SMALL (MSMALL * DIM)  // 262144

// ---------------------------------------------------------------------------
// Scratch (static device globals)
// ---------------------------------------------------------------------------
__device__ float g_FA[MN_SMALL];
__device__ float g_FB[MN_SMALL];
__device__ float g_SA[MN_SMALL];
__device__ float g_P[32 * MN_SMALL];             // split-K partials (32 MB)
__device__ unsigned short g_featsH[MN_SMALL];    // feats fp16
__device__ unsigned short g_TH[MN_SMALL];        // topk out fp16
__device__ unsigned short g_SAh[MN_SMALL];
__device__ unsigned short g_SBh[MN_SMALL];
__device__ unsigned short g_G3[MBIG * GEO];      // geo out fp16 (4 MB)
__device__ unsigned short g_H1[(size_t)MBIG * DIM];  // fp16, 64 MB
__device__ unsigned short g_H2[(size_t)MBIG * DIM];  // fp16, 64 MB
__device__ unsigned short g_W1[DIM * GEO];       // [N,K] w1 geo slice fp16
__device__ unsigned short g_W2[DIM * DIM];       // [N,K] fp16
__device__ unsigned short g_W3[DIM * DIM];       // [N,K] fp16
__device__ unsigned short g_WFA[DIM * DIM];      // pm_w1[0:1024] -> [N,K]
__device__ unsigned short g_WFB[DIM * DIM];      // pm_w1[1024:2048] -> [N,K]
__device__ unsigned short g_AG1[DIM * 2 * DIM];  // ag_w1 -> [1024, 2048]
__device__ unsigned short g_AG2[DIM * DIM];
__device__ unsigned short g_AG3[DIM * DIM];

// ---------------------------------------------------------------------------
// Helpers (sm_80+ only: cp.async, ldmatrix, mma.sync)
// ---------------------------------------------------------------------------
__device__ __forceinline__ uint32_t smem_u32(const void* p) {
    uint32_t a;
    asm("{ .reg .u64 t; cvta.to.shared.u64 t, %1; cvt.u32.u64 %0, t; }"
        : "=r"(a) : "l"(p));
    return a;
}
__device__ __forceinline__ void cp16(uint32_t dst, const void* src) {
    asm volatile("cp.async.cg.shared.global [%0], [%1], 16;" :: "r"(dst), "l"(src));
}
__device__ __forceinline__ void cp_commit() {
    asm volatile("cp.async.commit_group;" ::: "memory");
}
template<int N> __device__ __forceinline__ void cp_wait() {
    asm volatile("cp.async.wait_group %0;" :: "n"(N) : "memory");
}
#define SWZ128(o) ((o) ^ (((o) >> 3) & 0x70))

__device__ __forceinline__ void ldsm4(uint32_t& r0, uint32_t& r1,
                                      uint32_t& r2, uint32_t& r3, uint32_t addr) {
    asm volatile("ldmatrix.sync.aligned.m8n8.x4.shared.b16 {%0,%1,%2,%3}, [%4];"
                 : "=r"(r0), "=r"(r1), "=r"(r2), "=r"(r3) : "r"(addr));
}
__device__ __forceinline__ void mma_f16(float* c,
                                        const uint32_t* a, const uint32_t* b) {
    asm volatile("mma.sync.aligned.m16n8k16.row.col.f32.f16.f16.f32 "
                 "{%0,%1,%2,%3}, {%4,%5,%6,%7}, {%8,%9}, {%0,%1,%2,%3};"
                 : "+f"(c[0]), "+f"(c[1]), "+f"(c[2]), "+f"(c[3])
                 : "r"(a[0]), "r"(a[1]), "r"(a[2]), "r"(a[3]),
                   "r"(b[0]), "r"(b[1]));
}

__device__ __forceinline__ unsigned short f2h_bits(float v) {
    __half h = __float2half_rn(v);
    return *reinterpret_cast<unsigned short*>(&h);
}

// ---------------------------------------------------------------------------
// fp16 HMMA mainloop (128x128 CTA tile; 8 warps 2(M)x4(N); warp tile 64x32).
// Single __syncthreads per k-chunk (R13 config).
// ---------------------------------------------------------------------------
#define KCH 64
#define NKC (DIM / KCH)            // 16
#define STG_BYTES 32768
#define HMMA_SMEM (3 * STG_BYTES + 128)

struct HmmaCtx {
    uint32_t sbase;
    int tid, lane, wm, wn, mtile, ntile;
};

__device__ __forceinline__ void hmma_mainloop(
    const HmmaCtx& c,
    const unsigned short* __restrict__ A,
    const unsigned short* __restrict__ B,
    float acc[4][4][4])
{
#pragma unroll
    for (int mf = 0; mf < 4; mf++)
#pragma unroll
        for (int nf = 0; nf < 4; nf++)
#pragma unroll
            for (int e = 0; e < 4; e++) acc[mf][nf][e] = 0.f;

    auto load_chunk = [&](int kc, int stg) {
        const uint32_t s0 = c.sbase + (uint32_t)stg * STG_BYTES;
#pragma unroll
        for (int it = 0; it < 4; it++) {
            int t = c.tid + (it << 8);
            int rr = t >> 3, ss = t & 7;
            cp16(s0 + SWZ128((uint32_t)(rr * 128 + ss * 16)),
                 A + (size_t)((c.mtile << 7) + rr) * DIM + kc * KCH + ss * 8);
        }
#pragma unroll
        for (int it = 0; it < 4; it++) {
            int t = c.tid + (it << 8);
            int rr = t >> 3, ss = t & 7;
            cp16(s0 + 16384u + SWZ128((uint32_t)(rr * 128 + ss * 16)),
                 B + (size_t)((c.ntile << 7) + rr) * DIM + kc * KCH + ss * 8);
        }
        cp_commit();
    };

    const int a_rl = c.lane & 15;
    const int a_cl = (c.lane >> 4) << 3;
    const int b_rl = (c.lane & 7) + ((c.lane >> 4) << 3);
    const int b_cl = ((c.lane >> 3) & 1) << 3;

    auto compute = [&](int stg) {
        const uint32_t s0 = c.sbase + (uint32_t)stg * STG_BYTES;
        const uint32_t sA = s0, sB = s0 + 16384u;
#pragma unroll
        for (int ks = 0; ks < 4; ks++) {
            const int k0 = ks * 16;
            uint32_t bf[4][2];
#pragma unroll
            for (int np = 0; np < 2; np++) {
                const int n0 = c.wn * 32 + np * 16;
                const uint32_t off =
                    SWZ128((uint32_t)((n0 + b_rl) * 128 + (k0 + b_cl) * 2));
                uint32_t r0, r1, r2, r3;
                ldsm4(r0, r1, r2, r3, sB + off);
                bf[np * 2][0] = r0; bf[np * 2][1] = r1;
                bf[np * 2 + 1][0] = r2; bf[np * 2 + 1][1] = r3;
            }
            uint32_t af[4][4];
#pragma unroll
            for (int mf = 0; mf < 4; mf++) {
                const int m0 = c.wm * 64 + mf * 16;
                const uint32_t off =
                    SWZ128((uint32_t)((m0 + a_rl) * 128 + (k0 + a_cl) * 2));
                ldsm4(af[mf][0], af[mf][1], af[mf][2], af[mf][3], sA + off);
            }
#pragma unroll
            for (int mf = 0; mf < 4; mf++)
#pragma unroll
                for (int nf = 0; nf < 4; nf++)
                    mma_f16(acc[mf][nf], af[mf], bf[nf]);
        }
    };

    load_chunk(0, 0);
    load_chunk(1, 1);
    for (int kc = 0; kc < NKC; kc++) {
        if (kc + 1 < NKC) {
            cp_wait<1>();
        } else {
            cp_wait<0>();
        }
        __syncthreads();
        if (kc + 2 < NKC) load_chunk(kc + 2, (kc + 2) % 3);
        compute(kc % 3);
    }
}

// Layer 2: out = relu(A @ B^T + bias) -> fp16
__global__ void __launch_bounds__(256, 2)
hmma_l2_kernel(const unsigned short* __restrict__ A,
               const unsigned short* __restrict__ B,
               const float* __restrict__ bias,
               unsigned short* __restrict__ outH)
{
    extern __shared__ char smem_raw[];
    HmmaCtx c;
    c.sbase = (smem_u32(smem_raw) + 127u) & ~127u;
    c.tid = threadIdx.x;
    c.lane = c.tid & 31;
    const int w = c.tid >> 5;
    c.wm = w >> 2; c.wn = w & 3;
    c.mtile = blockIdx.y; c.ntile = blockIdx.x;

    float acc[4][4][4];
    hmma_mainloop(c, A, B, acc);

    const int rl = c.lane >> 2;
    const int cl = (c.lane & 3) << 1;
#pragma unroll
    for (int mf = 0; mf < 4; mf++) {
        const int m_base = (c.mtile << 7) + c.wm * 64 + mf * 16 + rl;
#pragma unroll
        for (int nf = 0; nf < 4; nf++) {
            const int n = (c.ntile << 7) + c.wn * 32 + nf * 8 + cl;
            const float b0 = bias[n], b1 = bias[n + 1];
#pragma unroll
            for (int half = 0; half < 2; half++) {
                const int m = m_base + half * 8;
                float v0 = fmaxf(acc[mf][nf][half * 2 + 0] + b0, 0.f);
                float v1 = fmaxf(acc[mf][nf][half * 2 + 1] + b1, 0.f);
                *(uint32_t*)(outH + (size_t)m * DIM + n) =
                    (uint32_t)f2h_bits(v0) | ((uint32_t)f2h_bits(v1) << 16);
            }
        }
    }
}

// Layer 3 fused with top-18-sum -> fp16 T
#define TPAD 132
#define L3_LISTS (128 * TPAD * 4)

__global__ void __launch_bounds__(256, 2)
hmma_l3_topk_kernel(const unsigned short* __restrict__ A,
                    const unsigned short* __restrict__ B,
                    const float* __restrict__ bias,
                    unsigned short* __restrict__ TH)
{
    extern __shared__ char smem_raw[];
    HmmaCtx c;
    c.sbase = (smem_u32(smem_raw) + 127u) & ~127u;
    c.tid = threadIdx.x;
    c.lane = c.tid & 31;
    const int w = c.tid >> 5;
    c.wm = w >> 2; c.wn = w & 3;
    c.mtile = blockIdx.y; c.ntile = blockIdx.x;

    float acc[4][4][4];
    hmma_mainloop(c, A, B, acc);
    __syncthreads();

    char* sm_c = smem_raw + (c.sbase - smem_u32(smem_raw));
    float* smf = (float*)sm_c;
    const int rl = c.lane >> 2;
    const int cl = (c.lane & 3) << 1;
#pragma unroll
    for (int mf = 0; mf < 4; mf++) {
        const int ml_base = c.wm * 64 + mf * 16 + rl;
#pragma unroll
        for (int nf = 0; nf < 4; nf++) {
            const int nl = c.wn * 32 + nf * 8 + cl;
            const int n = (c.ntile << 7) + nl;
            const float b0 = bias[n], b1 = bias[n + 1];
#pragma unroll
            for (int half = 0; half < 2; half++) {
                const int ml = ml_base + half * 8;
                smf[ml * TPAD + nl] = acc[mf][nf][half * 2 + 0] + b0;
                smf[ml * TPAD + nl + 1] = acc[mf][nf][half * 2 + 1] + b1;
            }
        }
    }
    __syncthreads();

    const int cidx = c.tid & 127;
    const int half = c.tid >> 7;
    float t18[TOPK];
#pragma unroll
    for (int s = 0; s < TOPK; s++) t18[s] = -3.4e38f;
    const float* colp = smf + half * 64 * TPAD + cidx;
    for (int j = 0; j < 64; j++) {
        float v = colp[j * TPAD];
        if (v > t18[TOPK - 1]) {
            t18[TOPK - 1] = v;
#pragma unroll
            for (int s = TOPK - 1; s > 0; s--) {
                if (t18[s] > t18[s - 1]) {
                    float tmp = t18[s - 1]; t18[s - 1] = t18[s]; t18[s] = tmp;
                }
            }
        }
    }
    float* lists = (float*)(sm_c + L3_LISTS);
    if (half == 1) {
#pragma unroll
        for (int s = 0; s < TOPK; s++) lists[cidx * TOPK + s] = t18[s];
    }
    __syncthreads();
    if (half == 0) {
#pragma unroll
        for (int s = 0; s < TOPK; s++) {
            float v = lists[cidx * TOPK + s];
            if (v > t18[TOPK - 1]) {
                t18[TOPK - 1] = v;
#pragma unroll
                for (int q = TOPK - 1; q > 0; q--) {
                    if (t18[q] > t18[q - 1]) {
                        float tmp = t18[q - 1]; t18[q - 1] = t18[q]; t18[q] = tmp;
                    }
                }
            }
        }
        float sum = 0.f;
#pragma unroll
        for (int s = 0; s < TOPK; s++) sum += t18[s];
        TH[(size_t)c.mtile * DIM + (c.ntile << 7) + cidx] =
            f2h_bits(sum * 0.125f);
    }
}

// ---------------------------------------------------------------------------
// Single-K-chunk (K=64) HMMA tile: shared by layer-1 and split-K small GEMMs.
// Loads A[128x64] from (Abase, row stride KA, col offset aoff) and
// B[128x64] from (Bbase, stride KB, col offset boff); computes 128x128 fp32.
// ---------------------------------------------------------------------------
#define L1_SMEM (2 * 16384 + 128)

__device__ __forceinline__ void hmma_k64_tile(
    uint32_t sbase, int tid, int lane, int wm, int wn,
    const unsigned short* __restrict__ Abase, int KA, int aoff, int mtile,
    const unsigned short* __restrict__ Bbase, int KB, int boff, int ntile,
    float acc[4][4][4])
{
#pragma unroll
    for (int it = 0; it < 4; it++) {
        int t = tid + (it << 8);
        int rr = t >> 3, ss = t & 7;
        cp16(sbase + SWZ128((uint32_t)(rr * 128 + ss * 16)),
             Abase + (size_t)((mtile << 7) + rr) * KA + aoff + ss * 8);
    }
#pragma unroll
    for (int it = 0; it < 4; it++) {
        int t = tid + (it << 8);
        int rr = t >> 3, ss = t & 7;
        cp16(sbase + 16384u + SWZ128((uint32_t)(rr * 128 + ss * 16)),
             Bbase + (size_t)((ntile << 7) + rr) * KB + boff + ss * 8);
    }
    cp_commit();

#pragma unroll
    for (int mf = 0; mf < 4; mf++)
#pragma unroll
        for (int nf = 0; nf < 4; nf++)
#pragma unroll
            for (int e = 0; e < 4; e++) acc[mf][nf][e] = 0.f;

    const int a_rl = lane & 15;
    const int a_cl = (lane >> 4) << 3;
    const int b_rl = (lane & 7) + ((lane >> 4) << 3);
    const int b_cl = ((lane >> 3) & 1) << 3;

    cp_wait<0>();
    __syncthreads();

    const uint32_t sA = sbase, sB = sbase + 16384u;
#pragma unroll
    for (int ks = 0; ks < 4; ks++) {
        const int k0 = ks * 16;
        uint32_t bf[4][2];
#pragma unroll
        for (int np = 0; np < 2; np++) {
            const int n0 = wn * 32 + np * 16;
            const uint32_t off =
                SWZ128((uint32_t)((n0 + b_rl) * 128 + (k0 + b_cl) * 2));
            uint32_t r0, r1, r2, r3;
            ldsm4(r0, r1, r2, r3, sB + off);
            bf[np * 2][0] = r0; bf[np * 2][1] = r1;
            bf[np * 2 + 1][0] = r2; bf[np * 2 + 1][1] = r3;
        }
        uint32_t af[4][4];
#pragma unroll
        for (int mf = 0; mf < 4; mf++) {
            const int m0 = wm * 64 + mf * 16;
            const uint32_t off =
                SWZ128((uint32_t)((m0 + a_rl) * 128 + (k0 + a_cl) * 2));
            ldsm4(af[mf][0], af[mf][1], af[mf][2], af[mf][3], sA + off);
        }
#pragma unroll
        for (int mf = 0; mf < 4; mf++)
#pragma unroll
            for (int nf = 0; nf < 4; nf++)
                mma_f16(acc[mf][nf], af[mf], bf[nf]);
    }
}

// Layer-1: H1 = relu( G3 @ W1g^T + FA_j + FB_i + b1 )
__global__ void __launch_bounds__(256, 3)
hmma_l1_kernel(const unsigned short* __restrict__ A,
               const unsigned short* __restrict__ B,
               const float* __restrict__ bias,
               const float* __restrict__ FA,
               const float* __restrict__ FB,
               unsigned short* __restrict__ outH)
{
    extern __shared__ char smem_raw[];
    const uint32_t sbase = (smem_u32(smem_raw) + 127u) & ~127u;
    const int tid = threadIdx.x;
    const int mtile = blockIdx.y, ntile = blockIdx.x;
    const int lane = tid & 31;
    const int w = tid >> 5;
    const int wm = w >> 2;
    const int wn = w & 3;

    float acc[4][4][4];
    hmma_k64_tile(sbase, tid, lane, wm, wn,
                  A, GEO, 0, mtile, B, GEO, 0, ntile, acc);

    const int rl = lane >> 2;
    const int cl = (lane & 3) << 1;
#pragma unroll
    for (int mf = 0; mf < 4; mf++) {
        const int m_base = (mtile << 7) + wm * 64 + mf * 16 + rl;
#pragma unroll
        for (int nf = 0; nf < 4; nf++) {
            const int n = (ntile << 7) + wn * 32 + nf * 8 + cl;
            const float b0 = bias[n], b1 = bias[n + 1];
#pragma unroll
            for (int half = 0; half < 2; half++) {
                const int m = m_base + half * 8;
                const int j = m & (NP - 1);
                const int bi = m >> 7;
                const int bb = bi >> 7;
                const float* aJ = FA + (size_t)((bb << 7) + j) * DIM;
                const float* aI = FB + (size_t)bi * DIM;
                float v0 = acc[mf][nf][half * 2 + 0] + b0 + aJ[n] + aI[n];
                float v1 = acc[mf][nf][half * 2 + 1] + b1 + aJ[n + 1] + aI[n + 1];
                v0 = fmaxf(v0, 0.f); v1 = fmaxf(v1, 0.f);
                *(uint32_t*)(outH + (size_t)m * DIM + n) =
                    (uint32_t)f2h_bits(v0) | ((uint32_t)f2h_bits(v1) << 16);
            }
        }
    }
}

// Split-K HMMA small GEMM: P[z] = A_sel[:, slice] @ B_sel[:, slice]^T
// mode 0: A0/B0, aslice=bslice=z
// mode 1: dual-B (A0; z<NS ? B0 : B1; aslice=bslice=z%NS)   [FA/FB]
// mode 2: dual-A (z<NS ? A0 : A1, aslice=z%NS; B0 with KB, bslice=z) [ag1]
__global__ void __launch_bounds__(256, 3)
hmma_sk_kernel(const unsigned short* __restrict__ A0,
               const unsigned short* __restrict__ A1,
               const unsigned short* __restrict__ B0,
               const unsigned short* __restrict__ B1,
               float* __restrict__ P, int KB, int NS, int mode)
{
    extern __shared__ char smem_raw[];
    const uint32_t sbase = (smem_u32(smem_raw) + 127u) & ~127u;
    const int tid = threadIdx.x;
    const int mtile = blockIdx.y, ntile = blockIdx.x;
    const int z = blockIdx.z;
    const int lane = tid & 31;
    const int w = tid >> 5;
    const int wm = w >> 2;
    const int wn = w & 3;

    const unsigned short* A = A0;
    const unsigned short* B = B0;
    int as = z, bs = z;
    if (mode == 1) {
        B = (z < NS) ? B0 : B1;
        as = bs = (z < NS) ? z : z - NS;
    } else if (mode == 2) {
        A = (z < NS) ? A0 : A1;
        as = (z < NS) ? z : z - NS;
    }

    float acc[4][4][4];
    hmma_k64_tile(sbase, tid, lane, wm, wn,
                  A, DIM, as * KCH, mtile, B, KB, bs * KCH, ntile, acc);

    float* Pp = P + (size_t)z * MN_SMALL;
    const int rl = lane >> 2;
    const int cl = (lane & 3) << 1;
#pragma unroll
    for (int mf = 0; mf < 4; mf++) {
        const int m_base = (mtile << 7) + wm * 64 + mf * 16 + rl;
#pragma unroll
        for (int nf = 0; nf < 4; nf++) {
            const int n = (ntile << 7) + wn * 32 + nf * 8 + cl;
#pragma unroll
            for (int half = 0; half < 2; half++) {
                const int m = m_base + half * 8;
                float2 v;
                v.x = acc[mf][nf][half * 2 + 0];
                v.y = acc[mf][nf][half * 2 + 1];
                *(float2*)(Pp + (size_t)m * DIM + n) = v;
            }
        }
    }
}

// ---------------------------------------------------------------------------
// Reductions over split-K partials
// ---------------------------------------------------------------------------
__global__ __launch_bounds__(256)
void skreduce(const float* __restrict__ P, int nsl,
              const float* __restrict__ bias, int relu,
              float* __restrict__ C, int MN, int N)
{
    int idx = blockIdx.x * blockDim.x + threadIdx.x;
    if (idx >= MN) return;
    float s = 0.f;
    for (int sl = 0; sl < nsl; sl++) s += P[(size_t)sl * MN + idx];
    if (bias) s += bias[idx % N];
    if (relu) s = fmaxf(s, 0.f);
    C[idx] = s;
}

__global__ __launch_bounds__(256)
void skreduce_h(const float* __restrict__ P, int nsl,
                const float* __restrict__ bias, int relu,
                unsigned short* __restrict__ C, int MN, int N)
{
    int idx = blockIdx.x * blockDim.x + threadIdx.x;
    if (idx >= MN) return;
    float s = 0.f;
    for (int sl = 0; sl < nsl; sl++) s += P[(size_t)sl * MN + idx];
    if (bias) s += bias[idx % N];
    if (relu) s = fmaxf(s, 0.f);
    C[idx] = f2h_bits(s);
}

__global__ __launch_bounds__(256)
void skreduce_dual(const float* __restrict__ P, int nsl,
                   float* __restrict__ C0, float* __restrict__ C1, int MN)
{
    int idx = blockIdx.x * blockDim.x + threadIdx.x;
    int which = idx >= MN;
    int base = which ? nsl : 0;
    int off = which ? idx - MN : idx;
    float s = 0.f;
    for (int sl = 0; sl < nsl; sl++)
        s += P[(size_t)(base + sl) * MN + off];
    if (which) C1[off] = s; else C0[off] = s;
}

// ---------------------------------------------------------------------------
// Weight transpose + fp16 convert:  W[Kd, Nd] -> Wh [Nd, Kd]
// ---------------------------------------------------------------------------
__global__ void wsplit_kernel(const float* __restrict__ W,
                              unsigned short* __restrict__ Wh,
                              int Kd, int Nd)
{
    __shared__ float tile[32][33];
    const int n0 = blockIdx.x * 32, k0 = blockIdx.y * 32;
    const int tx = threadIdx.x, ty = threadIdx.y;   // 32 x 8
#pragma unroll
    for (int i = 0; i < 32; i += 8)
        tile[ty + i][tx] = W[(size_t)(k0 + ty + i) * Nd + n0 + tx];
    __syncthreads();
#pragma unroll
    for (int i = 0; i < 32; i += 8) {
        Wh[(size_t)(n0 + ty + i) * Kd + k0 + tx] = f2h_bits(tile[tx][ty + i]);
    }
}

// fp32 -> fp16 elementwise
__global__ void h_convert_kernel(const float* __restrict__ X,
                                 unsigned short* __restrict__ Xh, int n)
{
    int idx = blockIdx.x * blockDim.x + threadIdx.x;
    if (idx < n) Xh[idx] = f2h_bits(X[idx]);
}

// ---------------------------------------------------------------------------
// Geo embedding + 3-layer 64-wide MLP (fused) -> fp16 output
// ---------------------------------------------------------------------------
__global__ __launch_bounds__(128)
void geo_kernel(const float* __restrict__ prop,
                const float* __restrict__ w1, const float* __restrict__ b1,
                const float* __restrict__ w2, const float* __restrict__ b2,
                const float* __restrict__ w3, const float* __restrict__ b3,
                unsigned short* __restrict__ G3)
{
    __shared__ float sw1[GEO * GEO], sw2[GEO * GEO], sw3[GEO * GEO];
    __shared__ float sb1[GEO], sb2[GEO], sb3[GEO];
    __shared__ float esm[128 * 65];

    const int tid = threadIdx.x;
    for (int t = tid; t < GEO * GEO; t += blockDim.x) {
        sw1[t] = w1[t]; sw2[t] = w2[t]; sw3[t] = w3[t];
    }
    for (int t = tid; t < GEO; t += blockDim.x) {
        sb1[t] = b1[t]; sb2[t] = b2[t]; sb3[t] = b3[t];
    }
    __syncthreads();

    const int row = blockIdx.x * blockDim.x + tid;
    const int b = row >> 14;
    const int i = (row >> 7) & (NP - 1);
    const int j = row & (NP - 1);

    const float* pi = prop + ((size_t)(b * NP + i)) * 4;
    const float* pj = prop + ((size_t)(b * NP + j)) * 4;
    float wi = pi[2] - pi[0] + 1.f, hi = pi[3] - pi[1] + 1.f;
    float wj = pj[2] - pj[0] + 1.f, hj = pj[3] - pj[1] + 1.f;
    float cxi = 0.5f * (pi[0] + pi[2]), cyi = 0.5f * (pi[1] + pi[3]);
    float cxj = 0.5f * (pj[0] + pj[2]), cyj = 0.5f * (pj[1] + pj[3]);

    float pos[4];
    pos[0] = (cxi - cxj) / wj;
    pos[1] = (cyi - cyj) / hj;
    pos[2] = wi / wj;
    pos[3] = hi / hj;

    const float dm[8] = {1.0f, 2.3713737f, 5.6234133f, 13.335215f,
                         31.622777f, 74.989421f, 177.82794f, 421.69650f};

    float* my = &esm[tid * 65];
#pragma unroll
    for (int p = 0; p < 4; p++) {
        float lp = logf(fmaxf(fabsf(pos[p]), 1e-3f)) * 100.f;
#pragma unroll
        for (int r = 0; r < 8; r++) {
            float arg = lp / dm[r];
            float s, c;
            sincosf(arg, &s, &c);
            my[p * 16 + r] = s;
            my[p * 16 + 8 + r] = c;
        }
    }

    float acc[GEO];
#pragma unroll
    for (int o = 0; o < GEO; o++) acc[o] = sb1[o];
    for (int k = 0; k < GEO; k++) {
        float ek = my[k];
        const float* wr = &sw1[k * GEO];
#pragma unroll
        for (int o = 0; o < GEO; o++) acc[o] = fmaf(ek, wr[o], acc[o]);
    }
#pragma unroll
    for (int o = 0; o < GEO; o++) my[o] = fmaxf(acc[o], 0.f);

#pragma unroll
    for (int o = 0; o < GEO; o++) acc[o] = sb2[o];
    for (int k = 0; k < GEO; k++) {
        float ek = my[k];
        const float* wr = &sw2[k * GEO];
#pragma unroll
        for (int o = 0; o < GEO; o++) acc[o] = fmaf(ek, wr[o], acc[o]);
    }
#pragma unroll
    for (int o = 0; o < GEO; o++) my[o] = fmaxf(acc[o], 0.f);

#pragma unroll
    for (int o = 0; o < GEO; o++) acc[o] = sb3[o];
    for (int k = 0; k < GEO; k++) {
        float ek = my[k];
        const float* wr = &sw3[k * GEO];
#pragma unroll
        for (int o = 0; o < GEO; o++) acc[o] = fmaf(ek, wr[o], acc[o]);
    }
    unsigned short* outp = G3 + (size_t)row * GEO;
#pragma unroll
    for (int o = 0; o < GEO; o++) outp[o] = f2h_bits(acc[o]);
}

// ---------------------------------------------------------------------------
// heads
// ---------------------------------------------------------------------------
__global__ __launch_bounds__(128)
void heads_kernel(const float* __restrict__ X,
                  const float* __restrict__ subject,
                  const float* __restrict__ obj,
                  const float* __restrict__ cs_w, const float* __restrict__ cs_b,
                  const float* __restrict__ cso_w, const float* __restrict__ cso_b,
                  float* __restrict__ out)
{
    int row = blockIdx.x;
    int b = row >> 7;
    int tid = threadIdx.x;

    float as = 0.f, ao = 0.f;
    for (int k = tid; k < DIM; k += 128) {
        float xv = X[(size_t)row * DIM + k];
        float sv = subject[(size_t)b * DIM + k];
        float ov = obj[(size_t)b * DIM + k];
        as += xv * cs_w[k] + sv * cs_w[DIM + k];
        ao += xv * cso_w[k] + ov * cso_w[DIM + k];
    }
    __shared__ float rs[128], ro[128];
    rs[tid] = as; ro[tid] = ao;
    __syncthreads();
    for (int s = 64; s > 0; s >>= 1) {
        if (tid < s) { rs[tid] += rs[tid + s]; ro[tid] += ro[tid + s]; }
        __syncthreads();
    }
    if (tid == 0) {
        float s1 = rs[0] + cs_b[0];
        float s2 = ro[0] + cso_b[0];
        out[row * 2 + 0] = 1.f / (1.f + expf(-s1));
        out[row * 2 + 1] = 1.f / (1.f + expf(-s2));
    }
}

// ---------------------------------------------------------------------------
// Launch
// ---------------------------------------------------------------------------
extern "C" void kernel_launch(void* const* d_in, const int* in_sizes, int n_in,
                              void* d_out, int out_size)
{
    const float* feats   = (const float*)d_in[0];
    const float* subject = (const float*)d_in[1];
    const float* obj     = (const float*)d_in[2];
    const float* prop    = (const float*)d_in[3];
    const float* gp_w1 = (const float*)d_in[4];
    const float* gp_b1 = (const float*)d_in[5];
    const float* gp_w2 = (const float*)d_in[6];
    const float* gp_b2 = (const float*)d_in[7];
    const float* gp_w3 = (const float*)d_in[8];
    const float* gp_b3 = (const float*)d_in[9];
    const float* pm_w1 = (const float*)d_in[10];
    const float* pm_b1 = (const float*)d_in[11];
    const float* pm_w2 = (const float*)d_in[12];
    const float* pm_b2 = (const float*)d_in[13];
    const float* pm_w3 = (const float*)d_in[14];
    const float* pm_b3 = (const float*)d_in[15];
    const float* ag_w1 = (const float*)d_in[16];
    const float* ag_b1 = (const float*)d_in[17];
    const float* ag_w2 = (const float*)d_in[18];
    const float* ag_b2 = (const float*)d_in[19];
    const float* ag_w3 = (const float*)d_in[20];
    const float* ag_b3 = (const float*)d_in[21];
    const float* cs_w  = (const float*)d_in[22];
    const float* cs_b  = (const float*)d_in[23];
    const float* cso_w = (const float*)d_in[24];
    const float* cso_b = (const float*)d_in[25];
    float* out = (float*)d_out;

    float *FA, *FB, *SA, *P;
    unsigned short *featsH, *TH, *SAh, *SBh;
    unsigned short *G3, *H1, *H2, *W1, *W2, *W3, *WFA, *WFB, *AG1, *AG2, *AG3;
    cudaGetSymbolAddress((void**)&FA, g_FA);
    cudaGetSymbolAddress((void**)&FB, g_FB);
    cudaGetSymbolAddress((void**)&SA, g_SA);
    cudaGetSymbolAddress((void**)&P,  g_P);
    cudaGetSymbolAddress((void**)&featsH, g_featsH);
    cudaGetSymbolAddress((void**)&TH, g_TH);
    cudaGetSymbolAddress((void**)&SAh, g_SAh);
    cudaGetSymbolAddress((void**)&SBh, g_SBh);
    cudaGetSymbolAddress((void**)&G3, g_G3);
    cudaGetSymbolAddress((void**)&H1, g_H1);
    cudaGetSymbolAddress((void**)&H2, g_H2);
    cudaGetSymbolAddress((void**)&W1, g_W1);
    cudaGetSymbolAddress((void**)&W2, g_W2);
    cudaGetSymbolAddress((void**)&W3, g_W3);
    cudaGetSymbolAddress((void**)&WFA, g_WFA);
    cudaGetSymbolAddress((void**)&WFB, g_WFB);
    cudaGetSymbolAddress((void**)&AG1, g_AG1);
    cudaGetSymbolAddress((void**)&AG2, g_AG2);
    cudaGetSymbolAddress((void**)&AG3, g_AG3);

    cudaFuncSetAttribute(hmma_l2_kernel,
                         cudaFuncAttributeMaxDynamicSharedMemorySize, HMMA_SMEM);
    cudaFuncSetAttribute(hmma_l3_topk_kernel,
                         cudaFuncAttributeMaxDynamicSharedMemorySize, HMMA_SMEM);
    cudaFuncSetAttribute(hmma_l1_kernel,
                         cudaFuncAttributeMaxDynamicSharedMemorySize, L1_SMEM);
    cudaFuncSetAttribute(hmma_sk_kernel,
                         cudaFuncAttributeMaxDynamicSharedMemorySize, L1_SMEM);

    dim3 ghm(DIM / 128, MBIG / 128);          // (8, 256)
    dim3 gws(DIM / 32, DIM / 32);
    dim3 gws1(DIM / 32, GEO / 32);
    dim3 gwsAG1(2 * DIM / 32, DIM / 32);      // (64, 32): note Wh dims
    const int MN = MN_SMALL;

    // ---- forked prologue ----
    cudaStream_t s1;
    cudaEvent_t eFork, eJoin, eJoin2;
    bool forked =
        (cudaStreamCreateWithFlags(&s1, cudaStreamNonBlocking) == cudaSuccess) &&
        (cudaEventCreateWithFlags(&eFork, cudaEventDisableTiming) == cudaSuccess) &&
        (cudaEventCreateWithFlags(&eJoin, cudaEventDisableTiming) == cudaSuccess) &&
        (cudaEventCreateWithFlags(&eJoin2, cudaEventDisableTiming) == cudaSuccess);

    if (forked) forked = (cudaEventRecord(eFork, 0) == cudaSuccess) &&
                         (cudaStreamWaitEvent(s1, eFork, 0) == cudaSuccess);

    cudaStream_t sb = forked ? s1 : 0;

    // branch B: W2/W3 convert + geo (feeds l2/l3 and l1's A operand)
    wsplit_kernel<<<gws, dim3(32, 8), 0, sb>>>(pm_w2, W2, DIM, DIM);
    wsplit_kernel<<<gws, dim3(32, 8), 0, sb>>>(pm_w3, W3, DIM, DIM);
    geo_kernel<<<MBIG / 128, 128, 0, sb>>>(prop, gp_w1, gp_b1, gp_w2, gp_b2,
                                           gp_w3, gp_b3, G3);
    if (forked) cudaEventRecord(eJoin, s1);

    // branch B (after join record): ag weight converts, overlap with l1/l2/l3
    wsplit_kernel<<<dim3(DIM / 32, 2 * DIM / 32), dim3(32, 8), 0, sb>>>(
        ag_w1, AG1, 2 * DIM, DIM);
    wsplit_kernel<<<gws, dim3(32, 8), 0, sb>>>(ag_w2, AG2, DIM, DIM);
    wsplit_kernel<<<gws, dim3(32, 8), 0, sb>>>(ag_w3, AG3, DIM, DIM);
    if (forked) cudaEventRecord(eJoin2, s1);

    // main branch: converts + FA/FB split-K HMMA
    h_convert_kernel<<<MN / 256, 256>>>(feats, featsH, MN);
    wsplit_kernel<<<gws1, dim3(32, 8)>>>(pm_w1 + (size_t)2 * DIM * DIM,
                                         W1, GEO, DIM);
    wsplit_kernel<<<gws, dim3(32, 8)>>>(pm_w1, WFA, DIM, DIM);
    wsplit_kernel<<<gws, dim3(32, 8)>>>(pm_w1 + (size_t)DIM * DIM, WFB, DIM, DIM);
    dim3 gsk32(DIM / 128, MSMALL / 128, 32);   // (8, 2, 32)
    hmma_sk_kernel<<<gsk32, 256, L1_SMEM>>>(featsH, nullptr, WFA, WFB,
                                            P, DIM, 16, 1);
    skreduce_dual<<<(2 * MN) / 256, 256>>>(P, 16, FA, FB, MN);

    if (forked) cudaStreamWaitEvent(0, eJoin, 0);

    // Pairwise layer 1 (fp16 HMMA, K=64) -> H1 fp16
    hmma_l1_kernel<<<ghm, 256, L1_SMEM>>>(G3, W1, pm_b1, FA, FB, H1);

    // Pairwise layer 2 (fp16 HMMA) -> H2 fp16, relu
    hmma_l2_kernel<<<ghm, 256, HMMA_SMEM>>>(H1, W2, pm_b2, H2);
    // Pairwise layer 3 + fused top-18 sum -> TH fp16
    hmma_l3_topk_kernel<<<ghm, 256, HMMA_SMEM>>>(H2, W3, pm_b3, TH);

    if (forked) cudaStreamWaitEvent(0, eJoin2, 0);

    // Aggregate MLP via HMMA split-K; ag1 = [featsH | TH] @ AG1 (dual-A)
    dim3 gsk16(DIM / 128, MSMALL / 128, 16);
    hmma_sk_kernel<<<gsk32, 256, L1_SMEM>>>(featsH, TH, AG1, nullptr,
                                            P, 2 * DIM, 16, 2);
    skreduce_h<<<MN / 256, 256>>>(P, 32, ag_b1, 1, SAh, MN, DIM);
    hmma_sk_kernel<<<gsk16, 256, L1_SMEM>>>(SAh, nullptr, AG2, nullptr,
                                            P, DIM, 16, 0);
    skreduce_h<<<MN / 256, 256>>>(P, 16, ag_b2, 1, SBh, MN, DIM);
    hmma_sk_kernel<<<gsk16, 256, L1_SMEM>>>(SBh, nullptr, AG3, nullptr,
                                            P, DIM, 16, 0);
    skreduce<<<MN / 256, 256>>>(P, 16, ag_b3, 0, SA, MN, DIM);

    // Heads
    heads_kernel<<<MSMALL, 128>>>(SA, subject, obj, cs_w, cs_b, cso_w, cso_b, out);
}